// round 6
// baseline (speedup 1.0000x reference)
#include <cuda_runtime.h>
#include <cuda.h>
#include <stdint.h>
#include <math.h>

#define BATCH 2
#define SEQ   2048
#define EMB   1024
#define NH    16
#define HD    64
#define DFF   4096
#define ROWS  (BATCH*SEQ)   // 4096

// ---------------- scratch (device globals; no allocation) ----------------
__device__ __align__(128) float g_xn   [ROWS * EMB];
__device__ __align__(128) float g_kqv  [ROWS * 3 * EMB];
__device__ __align__(128) float g_attn [ROWS * EMB];
__device__ __align__(128) float g_h    [ROWS * EMB];
__device__ __align__(128) float g_mid  [ROWS * DFF];
__device__ __align__(128) float g_wkqvT[3 * EMB * EMB];
__device__ __align__(128) float g_w1T  [DFF * EMB];
__device__ __align__(128) float g_w2T  [EMB * DFF];

// ====================== PTX helpers ========================================
__device__ __forceinline__ uint32_t smem_u32(const void* p) {
    uint32_t a;
    asm("{ .reg .u64 t; cvta.to.shared.u64 t, %1; cvt.u32.u64 %0, t; }"
        : "=r"(a) : "l"(p));
    return a;
}

__device__ __forceinline__ float tf32r(float x) {
    uint32_t u;
    asm("cvt.rna.tf32.f32 %0, %1;" : "=r"(u) : "f"(x));
    return __uint_as_float(u);
}

__device__ __forceinline__ float ex2(float x) {
    float y;
    asm("ex2.approx.f32 %0, %1;" : "=f"(y) : "f"(x));
    return y;
}

#define MBARRIER_INIT(addr, cnt) \
    asm volatile("mbarrier.init.shared.b64 [%0], %1;" :: "r"((uint32_t)(addr)), "r"((uint32_t)(cnt)) : "memory")

#define MBARRIER_ARRIVE(addr) \
    asm volatile("mbarrier.arrive.shared.b64 _, [%0];" :: "r"((uint32_t)(addr)) : "memory")

#define MBARRIER_EXPECT_TX(addr, bytes) \
    asm volatile("mbarrier.arrive.expect_tx.shared.b64 _, [%0], %1;" :: "r"((uint32_t)(addr)), "r"((uint32_t)(bytes)) : "memory")

#define MBARRIER_WAIT_PARITY(addr, ph) do { \
    uint32_t _m = (uint32_t)(addr); uint32_t _p = (uint32_t)(ph); uint32_t _d; \
    asm volatile("{\n\t.reg .pred p;\n\t" \
        "mbarrier.try_wait.parity.acquire.cta.shared::cta.b64 p, [%1], %2;\n\t" \
        "selp.b32 %0, 1, 0, p;\n\t}" : "=r"(_d) : "r"(_m), "r"(_p) : "memory"); \
    if (!_d) { \
        asm volatile("{\n\t.reg .pred P1;\n\t" \
            "WL_%=:\n\t" \
            "mbarrier.try_wait.parity.acquire.cta.shared::cta.b64 P1, [%0], %1, 0x989680;\n\t" \
            "@P1 bra.uni WD_%=;\n\t" \
            "bra.uni WL_%=;\n\t" \
            "WD_%=:\n\t}" :: "r"(_m), "r"(_p) : "memory"); \
    } \
} while (0)

#define MBARRIER_WAIT_PARITY_RELAXED(addr, ph) do { \
    uint32_t _m = (uint32_t)(addr); uint32_t _p = (uint32_t)(ph); uint32_t _d; \
    asm volatile("{\n\t.reg .pred p;\n\t" \
        "mbarrier.try_wait.parity.relaxed.cta.shared::cta.b64 p, [%1], %2, 0x989680;\n\t" \
        "selp.b32 %0, 1, 0, p;\n\t}" : "=r"(_d) : "r"(_m), "r"(_p) : "memory"); \
    if (!_d) { \
        asm volatile("{\n\t.reg .pred P1;\n\t" \
            "WL_%=:\n\t" \
            "mbarrier.try_wait.parity.relaxed.cta.shared::cta.b64 P1, [%0], %1, 0x989680;\n\t" \
            "@P1 bra.uni WD_%=;\n\t" \
            "bra.uni WL_%=;\n\t" \
            "WD_%=:\n\t}" :: "r"(_m), "r"(_p) : "memory"); \
    } \
} while (0)

#define TMA2D(smemaddr, mapptr, cx, cy, mbar) \
    asm volatile("cp.async.bulk.tensor.2d.shared::cta.global.tile.mbarrier::complete_tx::bytes " \
        "[%0], [%1, {%2, %3}], [%4];" \
        :: "r"((uint32_t)(smemaddr)), "l"(mapptr), "r"((int)(cx)), "r"((int)(cy)), \
           "r"((uint32_t)(mbar)) : "memory")

__device__ __forceinline__ float lds_f32(uint32_t addr) {
    float v;
    asm volatile("ld.shared.f32 %0, [%1];" : "=f"(v) : "r"(addr));
    return v;
}

__device__ __forceinline__ void cpasync16(uint32_t dst, const void* src) {
    asm volatile("cp.async.cg.shared.global [%0], [%1], 16;" :: "r"(dst), "l"(src));
}
#define CP_COMMIT() asm volatile("cp.async.commit_group;" ::: "memory")
#define CP_WAIT(n)  asm volatile("cp.async.wait_group %0;" :: "n"(n) : "memory")

__device__ __forceinline__ void mma_tf32(float* c, const float* a, const float* b) {
    asm volatile(
        "mma.sync.aligned.m16n8k8.row.col.f32.tf32.tf32.f32 "
        "{%0,%1,%2,%3}, {%4,%5,%6,%7}, {%8,%9}, {%0,%1,%2,%3};"
        : "+f"(c[0]), "+f"(c[1]), "+f"(c[2]), "+f"(c[3])
        : "r"(__float_as_uint(a[0])), "r"(__float_as_uint(a[1])),
          "r"(__float_as_uint(a[2])), "r"(__float_as_uint(a[3])),
          "r"(__float_as_uint(b[0])), "r"(__float_as_uint(b[1])));
}

// ====================== GEMM (TMA + mma.sync tf32) =========================
// 3 stages (99.3KB smem) -> 2 CTAs/SM for cross-CTA latency hiding
#define GBM 128
#define GBN 128
#define GBK 32
#define GS  3
#define STAGE_A_BYTES (GBM * GBK * 4)
#define STAGE_B_BYTES (GBN * GBK * 4)
#define STAGE_BYTES   (STAGE_A_BYTES + STAGE_B_BYTES)
#define SMEM_A_OFF(s) (1024 + (s) * STAGE_BYTES)
#define SMEM_B_OFF(s) (SMEM_A_OFF(s) + STAGE_A_BYTES)
#define GEMM_SMEM_TOTAL (1024 + GS * STAGE_BYTES)   // 99328

template <bool DO_BIAS, bool DO_RELU, bool DO_RESID, bool DO_TF32OUT>
__global__ __launch_bounds__(288, 2) void gemm_tf32_kernel(
    const __grid_constant__ CUtensorMap tmA,
    const __grid_constant__ CUtensorMap tmB,
    const float* __restrict__ bias,
    const float* __restrict__ resid,
    float*       __restrict__ C,
    int N, int K)
{
    extern __shared__ __align__(1024) char smem[];
    const uint32_t sb = smem_u32(smem);
    const int tid  = threadIdx.x;
    const int wid  = tid >> 5;
    const int lane = tid & 31;
    const int m0 = blockIdx.y * GBM;
    const int n0 = blockIdx.x * GBN;

    if (tid == 0) {
        #pragma unroll
        for (int s = 0; s < GS; s++) {
            MBARRIER_INIT(sb + 8 * s, 1);
            MBARRIER_INIT(sb + 64 + 8 * s, 8);
        }
    }
    __syncthreads();

    const int nk = K / GBK;

    if (wid == 8) {
        if (lane == 0) {
            int s = 0, eph = 0;   // eph = post-wrap phase; previous round = eph^1
            for (int j = 0; j < nk; j++) {
                if (j >= GS) MBARRIER_WAIT_PARITY_RELAXED(sb + 64 + 8 * s, eph ^ 1);
                MBARRIER_EXPECT_TX(sb + 8 * s, STAGE_BYTES);
                TMA2D(sb + SMEM_A_OFF(s), &tmA, j * GBK, m0, sb + 8 * s);
                TMA2D(sb + SMEM_B_OFF(s), &tmB, j * GBK, n0, sb + 8 * s);
                if (++s == GS) { s = 0; eph ^= 1; }
            }
        }
        return;
    }

    const int warp_m = wid >> 2;
    const int warp_n = wid & 3;
    const int g   = lane >> 2;
    const int tig = lane & 3;

    float acc[4][4][4];
    #pragma unroll
    for (int i = 0; i < 4; i++)
        #pragma unroll
        for (int j = 0; j < 4; j++)
            #pragma unroll
            for (int q = 0; q < 4; q++) acc[i][j][q] = 0.f;

    uint32_t aRowOff[4], aRowXor[4];
    #pragma unroll
    for (int mf = 0; mf < 4; mf++) {
        const int row = warp_m * 64 + mf * 16 + g;
        aRowOff[mf] = (uint32_t)row * 128;
        aRowXor[mf] = ((uint32_t)row & 7) << 4;
    }
    uint32_t bRowOff[4], bRowXor[4];
    #pragma unroll
    for (int nf = 0; nf < 4; nf++) {
        const int row = warp_n * 32 + nf * 8 + g;
        bRowOff[nf] = (uint32_t)row * 128;
        bRowXor[nf] = ((uint32_t)row & 7) << 4;
    }

    int s = 0, ph = 0;
    for (int i = 0; i < nk; i++) {
        MBARRIER_WAIT_PARITY(sb + 8 * s, ph);

        const uint32_t aB = sb + SMEM_A_OFF(s);
        const uint32_t bB = sb + SMEM_B_OFF(s);

        #pragma unroll
        for (int kf = 0; kf < 4; kf++) {
            const uint32_t k0b = (uint32_t)(kf * 8 + tig) * 4;
            const uint32_t k1b = k0b + 16;
            float a[4][4];
            #pragma unroll
            for (int mf = 0; mf < 4; mf++) {
                a[mf][0] = lds_f32(aB + aRowOff[mf] + (k0b ^ aRowXor[mf]));
                a[mf][1] = lds_f32(aB + aRowOff[mf] + 1024 + (k0b ^ aRowXor[mf]));
                a[mf][2] = lds_f32(aB + aRowOff[mf] + (k1b ^ aRowXor[mf]));
                a[mf][3] = lds_f32(aB + aRowOff[mf] + 1024 + (k1b ^ aRowXor[mf]));
            }
            float b[4][2];
            #pragma unroll
            for (int nf = 0; nf < 4; nf++) {
                b[nf][0] = lds_f32(bB + bRowOff[nf] + (k0b ^ bRowXor[nf]));
                b[nf][1] = lds_f32(bB + bRowOff[nf] + (k1b ^ bRowXor[nf]));
            }
            #pragma unroll
            for (int mf = 0; mf < 4; mf++)
                #pragma unroll
                for (int nf = 0; nf < 4; nf++)
                    mma_tf32(acc[mf][nf], a[mf], b[nf]);
        }

        __syncwarp();
        if (lane == 0) MBARRIER_ARRIVE(sb + 64 + 8 * s);
        if (++s == GS) { s = 0; ph ^= 1; }
    }

    #pragma unroll
    for (int mf = 0; mf < 4; mf++) {
        const int row0 = m0 + warp_m * 64 + mf * 16 + g;
        #pragma unroll
        for (int nf = 0; nf < 4; nf++) {
            const int col = n0 + warp_n * 32 + nf * 8 + 2 * tig;
            float2 v0 = make_float2(acc[mf][nf][0], acc[mf][nf][1]);
            float2 v1 = make_float2(acc[mf][nf][2], acc[mf][nf][3]);
            if (DO_BIAS) {
                float2 bb = *(const float2*)(bias + col);
                v0.x += bb.x; v0.y += bb.y; v1.x += bb.x; v1.y += bb.y;
            }
            if (DO_RELU) {
                v0.x = fmaxf(v0.x, 0.f); v0.y = fmaxf(v0.y, 0.f);
                v1.x = fmaxf(v1.x, 0.f); v1.y = fmaxf(v1.y, 0.f);
            }
            if (DO_TF32OUT) {
                v0.x = tf32r(v0.x); v0.y = tf32r(v0.y);
                v1.x = tf32r(v1.x); v1.y = tf32r(v1.y);
            }
            if (DO_RESID) {
                float2 r0 = *(const float2*)(resid + (size_t)row0 * N + col);
                float2 r1 = *(const float2*)(resid + (size_t)(row0 + 8) * N + col);
                v0.x += r0.x; v0.y += r0.y; v1.x += r1.x; v1.y += r1.y;
            }
            *(float2*)(C + (size_t)row0 * N + col)       = v0;
            *(float2*)(C + (size_t)(row0 + 8) * N + col) = v1;
        }
    }
}

// ====================== transpose [R,C] -> [C,R] (rounds to tf32) ==========
__global__ __launch_bounds__(256) void transpose_kernel(
    const float* __restrict__ in, float* __restrict__ out, int R, int C)
{
    __shared__ float t[32][33];
    const int bx = blockIdx.x * 32, by = blockIdx.y * 32;
    const int x = threadIdx.x, y = threadIdx.y;
    #pragma unroll
    for (int i = 0; i < 32; i += 8)
        t[y + i][x] = tf32r(in[(size_t)(by + y + i) * C + bx + x]);
    __syncthreads();
    #pragma unroll
    for (int i = 0; i < 32; i += 8)
        out[(size_t)(bx + y + i) * R + by + x] = t[x][y + i];
}

// ====================== LayerNorm (output rounded to tf32) =================
template <bool FUSE_ADD>
__global__ __launch_bounds__(256) void ln_kernel(
    const float* __restrict__ x,
    const float* __restrict__ addend,
    float*       __restrict__ resid_out,
    const float* __restrict__ gamma,
    const float* __restrict__ beta,
    float*       __restrict__ out)
{
    const int row = blockIdx.x;
    const int t   = threadIdx.x;
    const size_t base = (size_t)row * EMB;

    float4 v = *(const float4*)(x + base + t * 4);
    if (FUSE_ADD) {
        float4 a = *(const float4*)(addend + base + t * 4);
        v.x += a.x; v.y += a.y; v.z += a.z; v.w += a.w;
        *(float4*)(resid_out + base + t * 4) = v;
    }
    float s  = v.x + v.y + v.z + v.w;
    float ss = v.x*v.x + v.y*v.y + v.z*v.z + v.w*v.w;

    #pragma unroll
    for (int off = 16; off; off >>= 1) {
        s  += __shfl_down_sync(0xffffffffu, s,  off);
        ss += __shfl_down_sync(0xffffffffu, ss, off);
    }
    __shared__ float rs[8], rss[8];
    const int warp = t >> 5, lane = t & 31;
    if (lane == 0) { rs[warp] = s; rss[warp] = ss; }
    __syncthreads();
    if (t == 0) {
        float a = 0.f, b = 0.f;
        #pragma unroll
        for (int i = 0; i < 8; i++) { a += rs[i]; b += rss[i]; }
        rs[0] = a; rss[0] = b;
    }
    __syncthreads();
    const float mu  = rs[0] * (1.0f / EMB);
    const float var = rss[0] * (1.0f / EMB) - mu * mu;
    const float inv = rsqrtf(var + 1e-5f);

    float4 g  = *(const float4*)(gamma + t * 4);
    float4 b4 = *(const float4*)(beta  + t * 4);
    float4 o;
    o.x = tf32r((v.x - mu) * inv * g.x + b4.x);
    o.y = tf32r((v.y - mu) * inv * g.y + b4.y);
    o.z = tf32r((v.z - mu) * inv * g.z + b4.z);
    o.w = tf32r((v.w - mu) * inv * g.w + b4.w);
    *(float4*)(out + base + t * 4) = o;
}

// ====================== Flash attention (tensor cores) =====================
#define AT_KOFF(s) (17408 + (s) * 17408)
#define AT_VOFF(s) (52224 + (s) * 18432)
#define ATTN_SMEM  89088

__device__ __forceinline__ void load_kv(uint32_t sb, const float* __restrict__ kqv,
                                        int b, int h, int t, int buf, int tid)
{
    const float* base = kqv + ((size_t)(b * SEQ + t * 64)) * 3072 + h * 64;
    const uint32_t kd = sb + AT_KOFF(buf);
    const uint32_t vd = sb + AT_VOFF(buf);
    #pragma unroll
    for (int i = 0; i < 8; i++) {
        const int idx = tid + i * 128;
        const int row = idx >> 4, c4 = idx & 15;
        cpasync16(kd + (uint32_t)(row * 68 + c4 * 4) * 4, base + (size_t)row * 3072 + c4 * 4);
        cpasync16(vd + (uint32_t)(row * 72 + c4 * 4) * 4, base + (size_t)row * 3072 + 2048 + c4 * 4);
    }
}

__global__ __launch_bounds__(128) void attn_kernel(
    const float* __restrict__ kqv, float* __restrict__ out)
{
    extern __shared__ __align__(16) char asmem[];
    const uint32_t sb = smem_u32(asmem);
    // longest-first: high-bx blocks do the most key tiles; launch them first
    const int bx = (int)gridDim.x - 1 - (int)blockIdx.x;
    const int h = blockIdx.y, b = blockIdx.z;
    const int tid = threadIdx.x, w = tid >> 5, lane = tid & 31;
    const int tig = lane & 3, grp = lane >> 2;
    const float LOG2E = 1.4426950408889634f;
    const float slope2 = exp2f(-0.5f * (float)(h + 1)) * LOG2E;
    const int q0 = bx * 64;
    const int nt = bx + 1;

    {
        const float* qb = kqv + ((size_t)(b * SEQ + q0)) * 3072 + 1024 + h * 64;
        #pragma unroll
        for (int i = 0; i < 8; i++) {
            const int idx = tid + i * 128, row = idx >> 4, c4 = idx & 15;
            cpasync16(sb + (uint32_t)(row * 68 + c4 * 4) * 4, qb + (size_t)row * 3072 + c4 * 4);
        }
    }
    load_kv(sb, kqv, b, h, 0, 0, tid);
    CP_COMMIT();
    if (nt > 1) { load_kv(sb, kqv, b, h, 1, 1, tid); CP_COMMIT(); CP_WAIT(1); }
    else        { CP_WAIT(0); }
    __syncthreads();

    const float* Qs = (const float*)asmem;
    float qa[8][4];
    {
        const int r0 = w * 16 + grp;
        const float qs = LOG2E / 32.0f;
        #pragma unroll
        for (int kk = 0; kk < 8; kk++) {
            const int c = kk * 8 + tig;
            qa[kk][0] = Qs[r0 * 68 + c] * qs;
            qa[kk][1] = Qs[(r0 + 8) * 68 + c] * qs;
            qa[kk][2] = Qs[r0 * 68 + c + 4] * qs;
            qa[kk][3] = Qs[(r0 + 8) * 68 + c + 4] * qs;
        }
    }

    float o[8][4];
    #pragma unroll
    for (int nf = 0; nf < 8; nf++) { o[nf][0] = o[nf][1] = o[nf][2] = o[nf][3] = 0.f; }
    float m0 = -INFINITY, m1 = -INFINITY, l0 = 0.f, l1 = 0.f;
    const int qrow = q0 + w * 16 + grp;

    for (int t = 0; t < nt; t++) {
        const float* Ks = (const float*)(asmem + AT_KOFF(t & 1));
        const float* Vs = (const float*)(asmem + AT_VOFF(t & 1));
        const bool diag = (t == nt - 1);

        float s[8][4];
        #pragma unroll
        for (int nf = 0; nf < 8; nf++) { s[nf][0] = s[nf][1] = s[nf][2] = s[nf][3] = 0.f; }
        #pragma unroll
        for (int kk = 0; kk < 8; kk++) {
            #pragma unroll
            for (int nf = 0; nf < 8; nf++) {
                float bf[2];
                bf[0] = Ks[(nf * 8 + grp) * 68 + kk * 8 + tig];
                bf[1] = Ks[(nf * 8 + grp) * 68 + kk * 8 + tig + 4];
                mma_tf32(s[nf], qa[kk], bf);
            }
        }

        float mx0 = -INFINITY, mx1 = -INFINITY;
        #pragma unroll
        for (int nf = 0; nf < 8; nf++) {
            #pragma unroll
            for (int e = 0; e < 2; e++) {
                const int key = t * 64 + nf * 8 + 2 * tig + e;
                const float r0f = (float)(key - qrow);
                const float r1f = r0f - 8.0f;
                float v0 = s[nf][e]     + slope2 * r0f;
                float v1 = s[nf][e + 2] + slope2 * r1f;
                if (diag) {
                    if (r0f > 0.f) v0 = -1e30f;
                    if (r1f > 0.f) v1 = -1e30f;
                }
                s[nf][e] = v0; s[nf][e + 2] = v1;
                mx0 = fmaxf(mx0, v0); mx1 = fmaxf(mx1, v1);
            }
        }
        mx0 = fmaxf(mx0, __shfl_xor_sync(~0u, mx0, 1));
        mx0 = fmaxf(mx0, __shfl_xor_sync(~0u, mx0, 2));
        mx1 = fmaxf(mx1, __shfl_xor_sync(~0u, mx1, 1));
        mx1 = fmaxf(mx1, __shfl_xor_sync(~0u, mx1, 2));
        const float mn0 = fmaxf(m0, mx0), mn1 = fmaxf(m1, mx1);
        const float c0 = ex2(m0 - mn0), c1 = ex2(m1 - mn1);
        m0 = mn0; m1 = mn1;

        float rs0 = 0.f, rs1 = 0.f;
        #pragma unroll
        for (int nf = 0; nf < 8; nf++) {
            #pragma unroll
            for (int e = 0; e < 2; e++) {
                const float p0 = ex2(s[nf][e] - m0);
                const float p1 = ex2(s[nf][e + 2] - m1);
                s[nf][e] = p0; s[nf][e + 2] = p1;
                rs0 += p0; rs1 += p1;
            }
        }
        rs0 += __shfl_xor_sync(~0u, rs0, 1); rs0 += __shfl_xor_sync(~0u, rs0, 2);
        rs1 += __shfl_xor_sync(~0u, rs1, 1); rs1 += __shfl_xor_sync(~0u, rs1, 2);
        l0 = l0 * c0 + rs0; l1 = l1 * c1 + rs1;

        #pragma unroll
        for (int nf = 0; nf < 8; nf++) {
            o[nf][0] *= c0; o[nf][1] *= c0; o[nf][2] *= c1; o[nf][3] *= c1;
        }

        const int s1 = (lane & ~3) | (tig >> 1);
        const int s2 = s1 + 2;
        #pragma unroll
        for (int kk = 0; kk < 8; kk++) {
            const float v0 = __shfl_sync(~0u, s[kk][0], s1);
            const float v1 = __shfl_sync(~0u, s[kk][1], s1);
            const float v2 = __shfl_sync(~0u, s[kk][2], s1);
            const float v3 = __shfl_sync(~0u, s[kk][3], s1);
            const float w0 = __shfl_sync(~0u, s[kk][0], s2);
            const float w1 = __shfl_sync(~0u, s[kk][1], s2);
            const float w2 = __shfl_sync(~0u, s[kk][2], s2);
            const float w3 = __shfl_sync(~0u, s[kk][3], s2);
            float pa[4];
            pa[0] = (tig & 1) ? v1 : v0;
            pa[1] = (tig & 1) ? v3 : v2;
            pa[2] = (tig & 1) ? w1 : w0;
            pa[3] = (tig & 1) ? w3 : w2;
            #pragma unroll
            for (int nf = 0; nf < 8; nf++) {
                float bf[2];
                bf[0] = Vs[(kk * 8 + tig) * 72 + nf * 8 + grp];
                bf[1] = Vs[(kk * 8 + tig + 4) * 72 + nf * 8 + grp];
                mma_tf32(o[nf], pa, bf);
            }
        }

        __syncthreads();
        if (t + 1 < nt) {
            if (t + 2 < nt) { load_kv(sb, kqv, b, h, t + 2, t & 1, tid); CP_COMMIT(); CP_WAIT(1); }
            else            { CP_WAIT(0); }
            __syncthreads();
        }
    }

    const float il0 = 1.0f / l0, il1 = 1.0f / l1;
    float* op = out + ((size_t)(b * SEQ + qrow)) * EMB + h * 64;
    #pragma unroll
    for (int nf = 0; nf < 8; nf++) {
        const int col = nf * 8 + 2 * tig;
        float2 u0 = make_float2(o[nf][0] * il0, o[nf][1] * il0);
        float2 u1 = make_float2(o[nf][2] * il1, o[nf][3] * il1);
        *(float2*)(op + col) = u0;
        *(float2*)(op + (size_t)8 * EMB + col) = u1;
    }
}

// ====================== host: tensor maps ==================================
typedef CUresult (*EncodeTiledFn)(
    CUtensorMap*, CUtensorMapDataType, cuuint32_t, void*,
    const cuuint64_t*, const cuuint64_t*, const cuuint32_t*, const cuuint32_t*,
    CUtensorMapInterleave, CUtensorMapSwizzle, CUtensorMapL2promotion,
    CUtensorMapFloatOOBfill);

static void make_map(EncodeTiledFn enc, CUtensorMap* m, const float* p,
                     int K, int rows, int boxRows) {
    cuuint64_t dims[2]    = {(cuuint64_t)K, (cuuint64_t)rows};
    cuuint64_t strides[1] = {(cuuint64_t)K * 4};
    cuuint32_t box[2]     = {(cuuint32_t)GBK, (cuuint32_t)boxRows};
    cuuint32_t es[2]      = {1, 1};
    enc(m, CU_TENSOR_MAP_DATA_TYPE_FLOAT32, 2, (void*)p, dims, strides, box, es,
        CU_TENSOR_MAP_INTERLEAVE_NONE, CU_TENSOR_MAP_SWIZZLE_128B,
        CU_TENSOR_MAP_L2_PROMOTION_L2_128B, CU_TENSOR_MAP_FLOAT_OOB_FILL_NONE);
}

// ====================== driver =============================================
extern "C" void kernel_launch(void* const* d_in, const int* in_sizes, int n_in,
                              void* d_out, int out_size)
{
    const float* x     = (const float*)d_in[0];
    const float* w_kqv = (const float*)d_in[1];
    const float* ln1_g = (const float*)d_in[2];
    const float* ln1_b = (const float*)d_in[3];
    const float* ln2_g = (const float*)d_in[4];
    const float* ln2_b = (const float*)d_in[5];
    const float* w1    = (const float*)d_in[6];
    const float* b1    = (const float*)d_in[7];
    const float* w2    = (const float*)d_in[8];
    const float* b2    = (const float*)d_in[9];
    float* out = (float*)d_out;

    float *xn, *kqv, *attn, *hbuf, *mid, *wkqvT, *w1T, *w2T;
    cudaGetSymbolAddress((void**)&xn,    g_xn);
    cudaGetSymbolAddress((void**)&kqv,   g_kqv);
    cudaGetSymbolAddress((void**)&attn,  g_attn);
    cudaGetSymbolAddress((void**)&hbuf,  g_h);
    cudaGetSymbolAddress((void**)&mid,   g_mid);
    cudaGetSymbolAddress((void**)&wkqvT, g_wkqvT);
    cudaGetSymbolAddress((void**)&w1T,   g_w1T);
    cudaGetSymbolAddress((void**)&w2T,   g_w2T);

    EncodeTiledFn enc = nullptr;
    {
        cudaDriverEntryPointQueryResult st;
        cudaGetDriverEntryPointByVersion("cuTensorMapEncodeTiled", (void**)&enc,
                                         12000, cudaEnableDefault, &st);
    }

    alignas(64) CUtensorMap mA1, mB1, mA2, mB2, mA3, mB3;
    make_map(enc, &mA1, xn,    EMB, ROWS,    GBM);
    make_map(enc, &mB1, wkqvT, EMB, 3 * EMB, GBN);
    make_map(enc, &mA2, hbuf,  EMB, ROWS,    GBM);
    make_map(enc, &mB2, w1T,   EMB, DFF,     GBN);
    make_map(enc, &mA3, mid,   DFF, ROWS,    GBM);
    make_map(enc, &mB3, w2T,   DFF, EMB,     GBN);

    cudaFuncSetAttribute(gemm_tf32_kernel<false, false, false, true>,
                         cudaFuncAttributeMaxDynamicSharedMemorySize, GEMM_SMEM_TOTAL);
    cudaFuncSetAttribute(gemm_tf32_kernel<true, true, false, true>,
                         cudaFuncAttributeMaxDynamicSharedMemorySize, GEMM_SMEM_TOTAL);
    cudaFuncSetAttribute(gemm_tf32_kernel<true, false, true, false>,
                         cudaFuncAttributeMaxDynamicSharedMemorySize, GEMM_SMEM_TOTAL);
    cudaFuncSetAttribute(attn_kernel,
                         cudaFuncAttributeMaxDynamicSharedMemorySize, ATTN_SMEM);

    transpose_kernel<<<dim3(3 * EMB / 32, EMB / 32), dim3(32, 8)>>>(w_kqv, wkqvT, EMB, 3 * EMB);
    transpose_kernel<<<dim3(DFF / 32, EMB / 32), dim3(32, 8)>>>(w1, w1T, EMB, DFF);
    transpose_kernel<<<dim3(EMB / 32, DFF / 32), dim3(32, 8)>>>(w2, w2T, DFF, EMB);

    ln_kernel<false><<<ROWS, 256>>>(x, nullptr, nullptr, ln1_g, ln1_b, xn);

    gemm_tf32_kernel<false, false, false, true>
        <<<dim3(3 * EMB / GBN, ROWS / GBM), 288, GEMM_SMEM_TOTAL>>>(
            mA1, mB1, nullptr, nullptr, kqv, 3 * EMB, EMB);

    attn_kernel<<<dim3(SEQ / 64, NH, BATCH), 128, ATTN_SMEM>>>(kqv, attn);

    ln_kernel<true><<<ROWS, 256>>>(x, attn, out, ln2_g, ln2_b, hbuf);

    gemm_tf32_kernel<true, true, false, true>
        <<<dim3(DFF / GBN, ROWS / GBM), 288, GEMM_SMEM_TOTAL>>>(
            mA2, mB2, b1, nullptr, mid, DFF, EMB);

    gemm_tf32_kernel<true, false, true, false>
        <<<dim3(EMB / GBN, ROWS / GBM), 288, GEMM_SMEM_TOTAL>>>(
            mA3, mB3, b2, out, out, EMB, DFF);

    (void)in_sizes; (void)n_in; (void)out_size;
}

// round 7
// speedup vs baseline: 1.0020x; 1.0020x over previous
#include <cuda_runtime.h>
#include <cuda.h>
#include <stdint.h>
#include <math.h>

#define BATCH 2
#define SEQ   2048
#define EMB   1024
#define NH    16
#define HD    64
#define DFF   4096
#define ROWS  (BATCH*SEQ)   // 4096

// ---------------- scratch (device globals; no allocation) ----------------
__device__ __align__(128) float g_xn   [ROWS * EMB];
__device__ __align__(128) float g_kqv  [ROWS * 3 * EMB];
__device__ __align__(128) float g_attn [ROWS * EMB];
__device__ __align__(128) float g_h    [ROWS * EMB];
__device__ __align__(128) float g_mid  [ROWS * DFF];
__device__ __align__(128) float g_wkqvT[3 * EMB * EMB];
__device__ __align__(128) float g_w1T  [DFF * EMB];
__device__ __align__(128) float g_w2T  [EMB * DFF];

// ====================== PTX helpers ========================================
__device__ __forceinline__ uint32_t smem_u32(const void* p) {
    uint32_t a;
    asm("{ .reg .u64 t; cvta.to.shared.u64 t, %1; cvt.u32.u64 %0, t; }"
        : "=r"(a) : "l"(p));
    return a;
}

__device__ __forceinline__ float tf32r(float x) {
    uint32_t u;
    asm("cvt.rna.tf32.f32 %0, %1;" : "=r"(u) : "f"(x));
    return __uint_as_float(u);
}

__device__ __forceinline__ float ex2(float x) {
    float y;
    asm("ex2.approx.f32 %0, %1;" : "=f"(y) : "f"(x));
    return y;
}

#define MBARRIER_INIT(addr, cnt) \
    asm volatile("mbarrier.init.shared.b64 [%0], %1;" :: "r"((uint32_t)(addr)), "r"((uint32_t)(cnt)) : "memory")

#define MBARRIER_ARRIVE(addr) \
    asm volatile("mbarrier.arrive.shared.b64 _, [%0];" :: "r"((uint32_t)(addr)) : "memory")

#define MBARRIER_EXPECT_TX(addr, bytes) \
    asm volatile("mbarrier.arrive.expect_tx.shared.b64 _, [%0], %1;" :: "r"((uint32_t)(addr)), "r"((uint32_t)(bytes)) : "memory")

#define MBARRIER_WAIT_PARITY(addr, ph) do { \
    uint32_t _m = (uint32_t)(addr); uint32_t _p = (uint32_t)(ph); uint32_t _d; \
    asm volatile("{\n\t.reg .pred p;\n\t" \
        "mbarrier.try_wait.parity.acquire.cta.shared::cta.b64 p, [%1], %2;\n\t" \
        "selp.b32 %0, 1, 0, p;\n\t}" : "=r"(_d) : "r"(_m), "r"(_p) : "memory"); \
    if (!_d) { \
        asm volatile("{\n\t.reg .pred P1;\n\t" \
            "WL_%=:\n\t" \
            "mbarrier.try_wait.parity.acquire.cta.shared::cta.b64 P1, [%0], %1, 0x989680;\n\t" \
            "@P1 bra.uni WD_%=;\n\t" \
            "bra.uni WL_%=;\n\t" \
            "WD_%=:\n\t}" :: "r"(_m), "r"(_p) : "memory"); \
    } \
} while (0)

#define MBARRIER_WAIT_PARITY_RELAXED(addr, ph) do { \
    uint32_t _m = (uint32_t)(addr); uint32_t _p = (uint32_t)(ph); uint32_t _d; \
    asm volatile("{\n\t.reg .pred p;\n\t" \
        "mbarrier.try_wait.parity.relaxed.cta.shared::cta.b64 p, [%1], %2, 0x989680;\n\t" \
        "selp.b32 %0, 1, 0, p;\n\t}" : "=r"(_d) : "r"(_m), "r"(_p) : "memory"); \
    if (!_d) { \
        asm volatile("{\n\t.reg .pred P1;\n\t" \
            "WL_%=:\n\t" \
            "mbarrier.try_wait.parity.relaxed.cta.shared::cta.b64 P1, [%0], %1, 0x989680;\n\t" \
            "@P1 bra.uni WD_%=;\n\t" \
            "bra.uni WL_%=;\n\t" \
            "WD_%=:\n\t}" :: "r"(_m), "r"(_p) : "memory"); \
    } \
} while (0)

#define TMA2D(smemaddr, mapptr, cx, cy, mbar) \
    asm volatile("cp.async.bulk.tensor.2d.shared::cta.global.tile.mbarrier::complete_tx::bytes " \
        "[%0], [%1, {%2, %3}], [%4];" \
        :: "r"((uint32_t)(smemaddr)), "l"(mapptr), "r"((int)(cx)), "r"((int)(cy)), \
           "r"((uint32_t)(mbar)) : "memory")

__device__ __forceinline__ float lds_f32(uint32_t addr) {
    float v;
    asm volatile("ld.shared.f32 %0, [%1];" : "=f"(v) : "r"(addr));
    return v;
}

__device__ __forceinline__ void cpasync16(uint32_t dst, const void* src) {
    asm volatile("cp.async.cg.shared.global [%0], [%1], 16;" :: "r"(dst), "l"(src));
}
#define CP_COMMIT() asm volatile("cp.async.commit_group;" ::: "memory")
#define CP_WAIT(n)  asm volatile("cp.async.wait_group %0;" :: "n"(n) : "memory")

__device__ __forceinline__ void mma_tf32(float* c, const float* a, const float* b) {
    asm volatile(
        "mma.sync.aligned.m16n8k8.row.col.f32.tf32.tf32.f32 "
        "{%0,%1,%2,%3}, {%4,%5,%6,%7}, {%8,%9}, {%0,%1,%2,%3};"
        : "+f"(c[0]), "+f"(c[1]), "+f"(c[2]), "+f"(c[3])
        : "r"(__float_as_uint(a[0])), "r"(__float_as_uint(a[1])),
          "r"(__float_as_uint(a[2])), "r"(__float_as_uint(a[3])),
          "r"(__float_as_uint(b[0])), "r"(__float_as_uint(b[1])));
}

// ====================== GEMM (TMA + mma.sync tf32) =========================
// CTA tile 128x256, warp tile 64x64 -> halves smem-crossbar bytes per MAC
#define GBM 128
#define GBN 256
#define GBK 32
#define GS  4
#define STAGE_A_BYTES (GBM * GBK * 4)                 // 16384
#define STAGE_B_BYTES (GBN * GBK * 4)                 // 32768
#define STAGE_BYTES   (STAGE_A_BYTES + STAGE_B_BYTES) // 49152
#define SMEM_A_OFF(s) (1024 + (s) * STAGE_BYTES)
#define SMEM_B_OFF(s) (SMEM_A_OFF(s) + STAGE_A_BYTES)
#define GEMM_SMEM_TOTAL (1024 + GS * STAGE_BYTES)     // 197632

template <bool DO_BIAS, bool DO_RELU, bool DO_RESID, bool DO_TF32OUT>
__global__ __launch_bounds__(288, 1) void gemm_tf32_kernel(
    const __grid_constant__ CUtensorMap tmA,
    const __grid_constant__ CUtensorMap tmB,
    const float* __restrict__ bias,
    const float* __restrict__ resid,
    float*       __restrict__ C,
    int N, int K)
{
    extern __shared__ __align__(1024) char smem[];
    const uint32_t sb = smem_u32(smem);
    const int tid  = threadIdx.x;
    const int wid  = tid >> 5;
    const int lane = tid & 31;
    const int m0 = blockIdx.y * GBM;
    const int n0 = blockIdx.x * GBN;

    if (tid == 0) {
        #pragma unroll
        for (int s = 0; s < GS; s++) {
            MBARRIER_INIT(sb + 8 * s, 1);
            MBARRIER_INIT(sb + 64 + 8 * s, 8);
        }
    }
    __syncthreads();

    const int nk = K / GBK;

    if (wid == 8) {
        if (lane == 0) {
            int s = 0, eph = 0;   // eph = post-wrap phase; previous round = eph^1
            for (int j = 0; j < nk; j++) {
                if (j >= GS) MBARRIER_WAIT_PARITY_RELAXED(sb + 64 + 8 * s, eph ^ 1);
                MBARRIER_EXPECT_TX(sb + 8 * s, STAGE_BYTES);
                TMA2D(sb + SMEM_A_OFF(s), &tmA, j * GBK, m0, sb + 8 * s);
                TMA2D(sb + SMEM_B_OFF(s), &tmB, j * GBK, n0, sb + 8 * s);
                if (++s == GS) { s = 0; eph ^= 1; }
            }
        }
        return;
    }

    // consumer warps 0..7: warp tile 64(m) x 64(n); 2 x 4 warp grid
    const int warp_m = wid >> 2;   // 0..1
    const int warp_n = wid & 3;    // 0..3
    const int g   = lane >> 2;     // 0..7
    const int tig = lane & 3;      // 0..3

    float acc[4][8][4];
    #pragma unroll
    for (int i = 0; i < 4; i++)
        #pragma unroll
        for (int j = 0; j < 8; j++)
            #pragma unroll
            for (int q = 0; q < 4; q++) acc[i][j][q] = 0.f;

    uint32_t aRowOff[4], aRowXor[4];
    #pragma unroll
    for (int mf = 0; mf < 4; mf++) {
        const int row = warp_m * 64 + mf * 16 + g;
        aRowOff[mf] = (uint32_t)row * 128;
        aRowXor[mf] = ((uint32_t)row & 7) << 4;
    }
    uint32_t bRowOff[8], bRowXor[8];
    #pragma unroll
    for (int nf = 0; nf < 8; nf++) {
        const int row = warp_n * 64 + nf * 8 + g;
        bRowOff[nf] = (uint32_t)row * 128;
        bRowXor[nf] = ((uint32_t)row & 7) << 4;
    }

    int s = 0, ph = 0;
    for (int i = 0; i < nk; i++) {
        MBARRIER_WAIT_PARITY(sb + 8 * s, ph);

        const uint32_t aB = sb + SMEM_A_OFF(s);
        const uint32_t bB = sb + SMEM_B_OFF(s);

        #pragma unroll
        for (int kf = 0; kf < 4; kf++) {
            const uint32_t k0b = (uint32_t)(kf * 8 + tig) * 4;
            const uint32_t k1b = k0b + 16;
            float a[4][4];
            #pragma unroll
            for (int mf = 0; mf < 4; mf++) {
                a[mf][0] = lds_f32(aB + aRowOff[mf] + (k0b ^ aRowXor[mf]));
                a[mf][1] = lds_f32(aB + aRowOff[mf] + 1024 + (k0b ^ aRowXor[mf]));
                a[mf][2] = lds_f32(aB + aRowOff[mf] + (k1b ^ aRowXor[mf]));
                a[mf][3] = lds_f32(aB + aRowOff[mf] + 1024 + (k1b ^ aRowXor[mf]));
            }
            float b[8][2];
            #pragma unroll
            for (int nf = 0; nf < 8; nf++) {
                b[nf][0] = lds_f32(bB + bRowOff[nf] + (k0b ^ bRowXor[nf]));
                b[nf][1] = lds_f32(bB + bRowOff[nf] + (k1b ^ bRowXor[nf]));
            }
            #pragma unroll
            for (int mf = 0; mf < 4; mf++)
                #pragma unroll
                for (int nf = 0; nf < 8; nf++)
                    mma_tf32(acc[mf][nf], a[mf], b[nf]);
        }

        __syncwarp();
        if (lane == 0) MBARRIER_ARRIVE(sb + 64 + 8 * s);
        if (++s == GS) { s = 0; ph ^= 1; }
    }

    #pragma unroll
    for (int mf = 0; mf < 4; mf++) {
        const int row0 = m0 + warp_m * 64 + mf * 16 + g;
        #pragma unroll
        for (int nf = 0; nf < 8; nf++) {
            const int col = n0 + warp_n * 64 + nf * 8 + 2 * tig;
            float2 v0 = make_float2(acc[mf][nf][0], acc[mf][nf][1]);
            float2 v1 = make_float2(acc[mf][nf][2], acc[mf][nf][3]);
            if (DO_BIAS) {
                float2 bb = *(const float2*)(bias + col);
                v0.x += bb.x; v0.y += bb.y; v1.x += bb.x; v1.y += bb.y;
            }
            if (DO_RELU) {
                v0.x = fmaxf(v0.x, 0.f); v0.y = fmaxf(v0.y, 0.f);
                v1.x = fmaxf(v1.x, 0.f); v1.y = fmaxf(v1.y, 0.f);
            }
            if (DO_TF32OUT) {
                v0.x = tf32r(v0.x); v0.y = tf32r(v0.y);
                v1.x = tf32r(v1.x); v1.y = tf32r(v1.y);
            }
            if (DO_RESID) {
                float2 r0 = *(const float2*)(resid + (size_t)row0 * N + col);
                float2 r1 = *(const float2*)(resid + (size_t)(row0 + 8) * N + col);
                v0.x += r0.x; v0.y += r0.y; v1.x += r1.x; v1.y += r1.y;
            }
            *(float2*)(C + (size_t)row0 * N + col)       = v0;
            *(float2*)(C + (size_t)(row0 + 8) * N + col) = v1;
        }
    }
}

// ====================== transpose [R,C] -> [C,R] (rounds to tf32) ==========
__global__ __launch_bounds__(256) void transpose_kernel(
    const float* __restrict__ in, float* __restrict__ out, int R, int C)
{
    __shared__ float t[32][33];
    const int bx = blockIdx.x * 32, by = blockIdx.y * 32;
    const int x = threadIdx.x, y = threadIdx.y;
    #pragma unroll
    for (int i = 0; i < 32; i += 8)
        t[y + i][x] = tf32r(in[(size_t)(by + y + i) * C + bx + x]);
    __syncthreads();
    #pragma unroll
    for (int i = 0; i < 32; i += 8)
        out[(size_t)(bx + y + i) * R + by + x] = t[x][y + i];
}

// ====================== LayerNorm (output rounded to tf32) =================
template <bool FUSE_ADD>
__global__ __launch_bounds__(256) void ln_kernel(
    const float* __restrict__ x,
    const float* __restrict__ addend,
    float*       __restrict__ resid_out,
    const float* __restrict__ gamma,
    const float* __restrict__ beta,
    float*       __restrict__ out)
{
    const int row = blockIdx.x;
    const int t   = threadIdx.x;
    const size_t base = (size_t)row * EMB;

    float4 v = *(const float4*)(x + base + t * 4);
    if (FUSE_ADD) {
        float4 a = *(const float4*)(addend + base + t * 4);
        v.x += a.x; v.y += a.y; v.z += a.z; v.w += a.w;
        *(float4*)(resid_out + base + t * 4) = v;
    }
    float s  = v.x + v.y + v.z + v.w;
    float ss = v.x*v.x + v.y*v.y + v.z*v.z + v.w*v.w;

    #pragma unroll
    for (int off = 16; off; off >>= 1) {
        s  += __shfl_down_sync(0xffffffffu, s,  off);
        ss += __shfl_down_sync(0xffffffffu, ss, off);
    }
    __shared__ float rs[8], rss[8];
    const int warp = t >> 5, lane = t & 31;
    if (lane == 0) { rs[warp] = s; rss[warp] = ss; }
    __syncthreads();
    if (t == 0) {
        float a = 0.f, b = 0.f;
        #pragma unroll
        for (int i = 0; i < 8; i++) { a += rs[i]; b += rss[i]; }
        rs[0] = a; rss[0] = b;
    }
    __syncthreads();
    const float mu  = rs[0] * (1.0f / EMB);
    const float var = rss[0] * (1.0f / EMB) - mu * mu;
    const float inv = rsqrtf(var + 1e-5f);

    float4 g  = *(const float4*)(gamma + t * 4);
    float4 b4 = *(const float4*)(beta  + t * 4);
    float4 o;
    o.x = tf32r((v.x - mu) * inv * g.x + b4.x);
    o.y = tf32r((v.y - mu) * inv * g.y + b4.y);
    o.z = tf32r((v.z - mu) * inv * g.z + b4.z);
    o.w = tf32r((v.w - mu) * inv * g.w + b4.w);
    *(float4*)(out + base + t * 4) = o;
}

// ====================== Flash attention (tensor cores) =====================
#define AT_KOFF(s) (17408 + (s) * 17408)
#define AT_VOFF(s) (52224 + (s) * 18432)
#define ATTN_SMEM  89088

__device__ __forceinline__ void load_kv(uint32_t sb, const float* __restrict__ kqv,
                                        int b, int h, int t, int buf, int tid)
{
    const float* base = kqv + ((size_t)(b * SEQ + t * 64)) * 3072 + h * 64;
    const uint32_t kd = sb + AT_KOFF(buf);
    const uint32_t vd = sb + AT_VOFF(buf);
    #pragma unroll
    for (int i = 0; i < 8; i++) {
        const int idx = tid + i * 128;
        const int row = idx >> 4, c4 = idx & 15;
        cpasync16(kd + (uint32_t)(row * 68 + c4 * 4) * 4, base + (size_t)row * 3072 + c4 * 4);
        cpasync16(vd + (uint32_t)(row * 72 + c4 * 4) * 4, base + (size_t)row * 3072 + 2048 + c4 * 4);
    }
}

__global__ __launch_bounds__(128) void attn_kernel(
    const float* __restrict__ kqv, float* __restrict__ out)
{
    extern __shared__ __align__(16) char asmem[];
    const uint32_t sb = smem_u32(asmem);
    const int bx = (int)gridDim.x - 1 - (int)blockIdx.x;   // longest-first
    const int h = blockIdx.y, b = blockIdx.z;
    const int tid = threadIdx.x, w = tid >> 5, lane = tid & 31;
    const int tig = lane & 3, grp = lane >> 2;
    const float LOG2E = 1.4426950408889634f;
    const float slope2 = exp2f(-0.5f * (float)(h + 1)) * LOG2E;
    const int q0 = bx * 64;
    const int nt = bx + 1;

    {
        const float* qb = kqv + ((size_t)(b * SEQ + q0)) * 3072 + 1024 + h * 64;
        #pragma unroll
        for (int i = 0; i < 8; i++) {
            const int idx = tid + i * 128, row = idx >> 4, c4 = idx & 15;
            cpasync16(sb + (uint32_t)(row * 68 + c4 * 4) * 4, qb + (size_t)row * 3072 + c4 * 4);
        }
    }
    load_kv(sb, kqv, b, h, 0, 0, tid);
    CP_COMMIT();
    if (nt > 1) { load_kv(sb, kqv, b, h, 1, 1, tid); CP_COMMIT(); CP_WAIT(1); }
    else        { CP_WAIT(0); }
    __syncthreads();

    const float* Qs = (const float*)asmem;
    float qa[8][4];
    {
        const int r0 = w * 16 + grp;
        const float qs = LOG2E / 32.0f;
        #pragma unroll
        for (int kk = 0; kk < 8; kk++) {
            const int c = kk * 8 + tig;
            qa[kk][0] = Qs[r0 * 68 + c] * qs;
            qa[kk][1] = Qs[(r0 + 8) * 68 + c] * qs;
            qa[kk][2] = Qs[r0 * 68 + c + 4] * qs;
            qa[kk][3] = Qs[(r0 + 8) * 68 + c + 4] * qs;
        }
    }

    float o[8][4];
    #pragma unroll
    for (int nf = 0; nf < 8; nf++) { o[nf][0] = o[nf][1] = o[nf][2] = o[nf][3] = 0.f; }
    float m0 = -INFINITY, m1 = -INFINITY, l0 = 0.f, l1 = 0.f;
    const int qrow = q0 + w * 16 + grp;

    for (int t = 0; t < nt; t++) {
        const float* Ks = (const float*)(asmem + AT_KOFF(t & 1));
        const float* Vs = (const float*)(asmem + AT_VOFF(t & 1));
        const bool diag = (t == nt - 1);

        float s[8][4];
        #pragma unroll
        for (int nf = 0; nf < 8; nf++) { s[nf][0] = s[nf][1] = s[nf][2] = s[nf][3] = 0.f; }
        #pragma unroll
        for (int kk = 0; kk < 8; kk++) {
            #pragma unroll
            for (int nf = 0; nf < 8; nf++) {
                float bf[2];
                bf[0] = Ks[(nf * 8 + grp) * 68 + kk * 8 + tig];
                bf[1] = Ks[(nf * 8 + grp) * 68 + kk * 8 + tig + 4];
                mma_tf32(s[nf], qa[kk], bf);
            }
        }

        float mx0 = -INFINITY, mx1 = -INFINITY;
        #pragma unroll
        for (int nf = 0; nf < 8; nf++) {
            #pragma unroll
            for (int e = 0; e < 2; e++) {
                const int key = t * 64 + nf * 8 + 2 * tig + e;
                const float r0f = (float)(key - qrow);
                const float r1f = r0f - 8.0f;
                float v0 = s[nf][e]     + slope2 * r0f;
                float v1 = s[nf][e + 2] + slope2 * r1f;
                if (diag) {
                    if (r0f > 0.f) v0 = -1e30f;
                    if (r1f > 0.f) v1 = -1e30f;
                }
                s[nf][e] = v0; s[nf][e + 2] = v1;
                mx0 = fmaxf(mx0, v0); mx1 = fmaxf(mx1, v1);
            }
        }
        mx0 = fmaxf(mx0, __shfl_xor_sync(~0u, mx0, 1));
        mx0 = fmaxf(mx0, __shfl_xor_sync(~0u, mx0, 2));
        mx1 = fmaxf(mx1, __shfl_xor_sync(~0u, mx1, 1));
        mx1 = fmaxf(mx1, __shfl_xor_sync(~0u, mx1, 2));
        const float mn0 = fmaxf(m0, mx0), mn1 = fmaxf(m1, mx1);
        const float c0 = ex2(m0 - mn0), c1 = ex2(m1 - mn1);
        m0 = mn0; m1 = mn1;

        float rs0 = 0.f, rs1 = 0.f;
        #pragma unroll
        for (int nf = 0; nf < 8; nf++) {
            #pragma unroll
            for (int e = 0; e < 2; e++) {
                const float p0 = ex2(s[nf][e] - m0);
                const float p1 = ex2(s[nf][e + 2] - m1);
                s[nf][e] = p0; s[nf][e + 2] = p1;
                rs0 += p0; rs1 += p1;
            }
        }
        rs0 += __shfl_xor_sync(~0u, rs0, 1); rs0 += __shfl_xor_sync(~0u, rs0, 2);
        rs1 += __shfl_xor_sync(~0u, rs1, 1); rs1 += __shfl_xor_sync(~0u, rs1, 2);
        l0 = l0 * c0 + rs0; l1 = l1 * c1 + rs1;

        #pragma unroll
        for (int nf = 0; nf < 8; nf++) {
            o[nf][0] *= c0; o[nf][1] *= c0; o[nf][2] *= c1; o[nf][3] *= c1;
        }

        const int s1 = (lane & ~3) | (tig >> 1);
        const int s2 = s1 + 2;
        #pragma unroll
        for (int kk = 0; kk < 8; kk++) {
            const float v0 = __shfl_sync(~0u, s[kk][0], s1);
            const float v1 = __shfl_sync(~0u, s[kk][1], s1);
            const float v2 = __shfl_sync(~0u, s[kk][2], s1);
            const float v3 = __shfl_sync(~0u, s[kk][3], s1);
            const float w0 = __shfl_sync(~0u, s[kk][0], s2);
            const float w1 = __shfl_sync(~0u, s[kk][1], s2);
            const float w2 = __shfl_sync(~0u, s[kk][2], s2);
            const float w3 = __shfl_sync(~0u, s[kk][3], s2);
            float pa[4];
            pa[0] = (tig & 1) ? v1 : v0;
            pa[1] = (tig & 1) ? v3 : v2;
            pa[2] = (tig & 1) ? w1 : w0;
            pa[3] = (tig & 1) ? w3 : w2;
            #pragma unroll
            for (int nf = 0; nf < 8; nf++) {
                float bf[2];
                bf[0] = Vs[(kk * 8 + tig) * 72 + nf * 8 + grp];
                bf[1] = Vs[(kk * 8 + tig + 4) * 72 + nf * 8 + grp];
                mma_tf32(o[nf], pa, bf);
            }
        }

        __syncthreads();
        if (t + 1 < nt) {
            if (t + 2 < nt) { load_kv(sb, kqv, b, h, t + 2, t & 1, tid); CP_COMMIT(); CP_WAIT(1); }
            else            { CP_WAIT(0); }
            __syncthreads();
        }
    }

    const float il0 = 1.0f / l0, il1 = 1.0f / l1;
    float* op = out + ((size_t)(b * SEQ + qrow)) * EMB + h * 64;
    #pragma unroll
    for (int nf = 0; nf < 8; nf++) {
        const int col = nf * 8 + 2 * tig;
        float2 u0 = make_float2(o[nf][0] * il0, o[nf][1] * il0);
        float2 u1 = make_float2(o[nf][2] * il1, o[nf][3] * il1);
        *(float2*)(op + col) = u0;
        *(float2*)(op + (size_t)8 * EMB + col) = u1;
    }
}

// ====================== host: tensor maps ==================================
typedef CUresult (*EncodeTiledFn)(
    CUtensorMap*, CUtensorMapDataType, cuuint32_t, void*,
    const cuuint64_t*, const cuuint64_t*, const cuuint32_t*, const cuuint32_t*,
    CUtensorMapInterleave, CUtensorMapSwizzle, CUtensorMapL2promotion,
    CUtensorMapFloatOOBfill);

static void make_map(EncodeTiledFn enc, CUtensorMap* m, const float* p,
                     int K, int rows, int boxRows) {
    cuuint64_t dims[2]    = {(cuuint64_t)K, (cuuint64_t)rows};
    cuuint64_t strides[1] = {(cuuint64_t)K * 4};
    cuuint32_t box[2]     = {(cuuint32_t)GBK, (cuuint32_t)boxRows};
    cuuint32_t es[2]      = {1, 1};
    enc(m, CU_TENSOR_MAP_DATA_TYPE_FLOAT32, 2, (void*)p, dims, strides, box, es,
        CU_TENSOR_MAP_INTERLEAVE_NONE, CU_TENSOR_MAP_SWIZZLE_128B,
        CU_TENSOR_MAP_L2_PROMOTION_L2_128B, CU_TENSOR_MAP_FLOAT_OOB_FILL_NONE);
}

// ====================== driver =============================================
extern "C" void kernel_launch(void* const* d_in, const int* in_sizes, int n_in,
                              void* d_out, int out_size)
{
    const float* x     = (const float*)d_in[0];
    const float* w_kqv = (const float*)d_in[1];
    const float* ln1_g = (const float*)d_in[2];
    const float* ln1_b = (const float*)d_in[3];
    const float* ln2_g = (const float*)d_in[4];
    const float* ln2_b = (const float*)d_in[5];
    const float* w1    = (const float*)d_in[6];
    const float* b1    = (const float*)d_in[7];
    const float* w2    = (const float*)d_in[8];
    const float* b2    = (const float*)d_in[9];
    float* out = (float*)d_out;

    float *xn, *kqv, *attn, *hbuf, *mid, *wkqvT, *w1T, *w2T;
    cudaGetSymbolAddress((void**)&xn,    g_xn);
    cudaGetSymbolAddress((void**)&kqv,   g_kqv);
    cudaGetSymbolAddress((void**)&attn,  g_attn);
    cudaGetSymbolAddress((void**)&hbuf,  g_h);
    cudaGetSymbolAddress((void**)&mid,   g_mid);
    cudaGetSymbolAddress((void**)&wkqvT, g_wkqvT);
    cudaGetSymbolAddress((void**)&w1T,   g_w1T);
    cudaGetSymbolAddress((void**)&w2T,   g_w2T);

    EncodeTiledFn enc = nullptr;
    {
        cudaDriverEntryPointQueryResult st;
        cudaGetDriverEntryPointByVersion("cuTensorMapEncodeTiled", (void**)&enc,
                                         12000, cudaEnableDefault, &st);
    }

    alignas(64) CUtensorMap mA1, mB1, mA2, mB2, mA3, mB3;
    make_map(enc, &mA1, xn,    EMB, ROWS,    GBM);
    make_map(enc, &mB1, wkqvT, EMB, 3 * EMB, GBN);
    make_map(enc, &mA2, hbuf,  EMB, ROWS,    GBM);
    make_map(enc, &mB2, w1T,   EMB, DFF,     GBN);
    make_map(enc, &mA3, mid,   DFF, ROWS,    GBM);
    make_map(enc, &mB3, w2T,   DFF, EMB,     GBN);

    cudaFuncSetAttribute(gemm_tf32_kernel<false, false, false, true>,
                         cudaFuncAttributeMaxDynamicSharedMemorySize, GEMM_SMEM_TOTAL);
    cudaFuncSetAttribute(gemm_tf32_kernel<true, true, false, true>,
                         cudaFuncAttributeMaxDynamicSharedMemorySize, GEMM_SMEM_TOTAL);
    cudaFuncSetAttribute(gemm_tf32_kernel<true, false, true, false>,
                         cudaFuncAttributeMaxDynamicSharedMemorySize, GEMM_SMEM_TOTAL);
    cudaFuncSetAttribute(attn_kernel,
                         cudaFuncAttributeMaxDynamicSharedMemorySize, ATTN_SMEM);

    transpose_kernel<<<dim3(3 * EMB / 32, EMB / 32), dim3(32, 8)>>>(w_kqv, wkqvT, EMB, 3 * EMB);
    transpose_kernel<<<dim3(DFF / 32, EMB / 32), dim3(32, 8)>>>(w1, w1T, EMB, DFF);
    transpose_kernel<<<dim3(EMB / 32, DFF / 32), dim3(32, 8)>>>(w2, w2T, DFF, EMB);

    ln_kernel<false><<<ROWS, 256>>>(x, nullptr, nullptr, ln1_g, ln1_b, xn);

    gemm_tf32_kernel<false, false, false, true>
        <<<dim3(3 * EMB / GBN, ROWS / GBM), 288, GEMM_SMEM_TOTAL>>>(
            mA1, mB1, nullptr, nullptr, kqv, 3 * EMB, EMB);

    attn_kernel<<<dim3(SEQ / 64, NH, BATCH), 128, ATTN_SMEM>>>(kqv, attn);

    ln_kernel<true><<<ROWS, 256>>>(x, attn, out, ln2_g, ln2_b, hbuf);

    gemm_tf32_kernel<true, true, false, true>
        <<<dim3(DFF / GBN, ROWS / GBM), 288, GEMM_SMEM_TOTAL>>>(
            mA2, mB2, b1, nullptr, mid, DFF, EMB);

    gemm_tf32_kernel<true, false, true, false>
        <<<dim3(EMB / GBN, ROWS / GBM), 288, GEMM_SMEM_TOTAL>>>(
            mA3, mB3, b2, out, out, EMB, DFF);

    (void)in_sizes; (void)n_in; (void)out_size;
}

// round 8
// speedup vs baseline: 1.4531x; 1.4502x over previous
#include <cuda_runtime.h>
#include <cuda.h>
#include <cuda_fp16.h>
#include <stdint.h>
#include <math.h>

#define BATCH 2
#define SEQ   2048
#define EMB   1024
#define NH    16
#define HD    64
#define DFF   4096
#define ROWS  (BATCH*SEQ)   // 4096

// ---------------- scratch (device globals; no allocation) ----------------
__device__ __align__(128) __half g_xn   [ROWS * EMB];
__device__ __align__(128) float  g_kqv  [ROWS * 3 * EMB];
__device__ __align__(128) float  g_attn [ROWS * EMB];
__device__ __align__(128) __half g_h    [ROWS * EMB];
__device__ __align__(128) __half g_mid  [ROWS * DFF];
__device__ __align__(128) __half g_wkqvT[3 * EMB * EMB];
__device__ __align__(128) __half g_w1T  [DFF * EMB];
__device__ __align__(128) __half g_w2T  [EMB * DFF];

// ====================== PTX helpers ========================================
__device__ __forceinline__ uint32_t smem_u32(const void* p) {
    uint32_t a;
    asm("{ .reg .u64 t; cvta.to.shared.u64 t, %1; cvt.u32.u64 %0, t; }"
        : "=r"(a) : "l"(p));
    return a;
}

__device__ __forceinline__ float tf32r(float x) {
    uint32_t u;
    asm("cvt.rna.tf32.f32 %0, %1;" : "=r"(u) : "f"(x));
    return __uint_as_float(u);
}

__device__ __forceinline__ float ex2(float x) {
    float y;
    asm("ex2.approx.f32 %0, %1;" : "=f"(y) : "f"(x));
    return y;
}

#define MBARRIER_INIT(addr, cnt) \
    asm volatile("mbarrier.init.shared.b64 [%0], %1;" :: "r"((uint32_t)(addr)), "r"((uint32_t)(cnt)) : "memory")

#define MBARRIER_ARRIVE(addr) \
    asm volatile("mbarrier.arrive.shared.b64 _, [%0];" :: "r"((uint32_t)(addr)) : "memory")

#define MBARRIER_EXPECT_TX(addr, bytes) \
    asm volatile("mbarrier.arrive.expect_tx.shared.b64 _, [%0], %1;" :: "r"((uint32_t)(addr)), "r"((uint32_t)(bytes)) : "memory")

#define MBARRIER_WAIT_PARITY(addr, ph) do { \
    uint32_t _m = (uint32_t)(addr); uint32_t _p = (uint32_t)(ph); uint32_t _d; \
    asm volatile("{\n\t.reg .pred p;\n\t" \
        "mbarrier.try_wait.parity.acquire.cta.shared::cta.b64 p, [%1], %2;\n\t" \
        "selp.b32 %0, 1, 0, p;\n\t}" : "=r"(_d) : "r"(_m), "r"(_p) : "memory"); \
    if (!_d) { \
        asm volatile("{\n\t.reg .pred P1;\n\t" \
            "WL_%=:\n\t" \
            "mbarrier.try_wait.parity.acquire.cta.shared::cta.b64 P1, [%0], %1, 0x989680;\n\t" \
            "@P1 bra.uni WD_%=;\n\t" \
            "bra.uni WL_%=;\n\t" \
            "WD_%=:\n\t}" :: "r"(_m), "r"(_p) : "memory"); \
    } \
} while (0)

#define MBARRIER_WAIT_PARITY_RELAXED(addr, ph) do { \
    uint32_t _m = (uint32_t)(addr); uint32_t _p = (uint32_t)(ph); uint32_t _d; \
    asm volatile("{\n\t.reg .pred p;\n\t" \
        "mbarrier.try_wait.parity.relaxed.cta.shared::cta.b64 p, [%1], %2, 0x989680;\n\t" \
        "selp.b32 %0, 1, 0, p;\n\t}" : "=r"(_d) : "r"(_m), "r"(_p) : "memory"); \
    if (!_d) { \
        asm volatile("{\n\t.reg .pred P1;\n\t" \
            "WL_%=:\n\t" \
            "mbarrier.try_wait.parity.relaxed.cta.shared::cta.b64 P1, [%0], %1, 0x989680;\n\t" \
            "@P1 bra.uni WD_%=;\n\t" \
            "bra.uni WL_%=;\n\t" \
            "WD_%=:\n\t}" :: "r"(_m), "r"(_p) : "memory"); \
    } \
} while (0)

#define TMA2D(smemaddr, mapptr, cx, cy, mbar) \
    asm volatile("cp.async.bulk.tensor.2d.shared::cta.global.tile.mbarrier::complete_tx::bytes " \
        "[%0], [%1, {%2, %3}], [%4];" \
        :: "r"((uint32_t)(smemaddr)), "l"(mapptr), "r"((int)(cx)), "r"((int)(cy)), \
           "r"((uint32_t)(mbar)) : "memory")

__device__ __forceinline__ uint32_t lds_u32(uint32_t addr) {
    uint32_t v;
    asm volatile("ld.shared.b32 %0, [%1];" : "=r"(v) : "r"(addr));
    return v;
}

__device__ __forceinline__ void cpasync16(uint32_t dst, const void* src) {
    asm volatile("cp.async.cg.shared.global [%0], [%1], 16;" :: "r"(dst), "l"(src));
}
#define CP_COMMIT() asm volatile("cp.async.commit_group;" ::: "memory")
#define CP_WAIT(n)  asm volatile("cp.async.wait_group %0;" :: "n"(n) : "memory")

// fp16 mma m16n8k16, fp32 accumulate (legacy tensor pipe, 2x tf32 MAC rate)
__device__ __forceinline__ void mma_f16(float* c, const uint32_t* a, const uint32_t* b) {
    asm volatile(
        "mma.sync.aligned.m16n8k16.row.col.f32.f16.f16.f32 "
        "{%0,%1,%2,%3}, {%4,%5,%6,%7}, {%8,%9}, {%0,%1,%2,%3};"
        : "+f"(c[0]), "+f"(c[1]), "+f"(c[2]), "+f"(c[3])
        : "r"(a[0]), "r"(a[1]), "r"(a[2]), "r"(a[3]),
          "r"(b[0]), "r"(b[1]));
}

// tf32 mma (attention only)
__device__ __forceinline__ void mma_tf32(float* c, const float* a, const float* b) {
    asm volatile(
        "mma.sync.aligned.m16n8k8.row.col.f32.tf32.tf32.f32 "
        "{%0,%1,%2,%3}, {%4,%5,%6,%7}, {%8,%9}, {%0,%1,%2,%3};"
        : "+f"(c[0]), "+f"(c[1]), "+f"(c[2]), "+f"(c[3])
        : "r"(__float_as_uint(a[0])), "r"(__float_as_uint(a[1])),
          "r"(__float_as_uint(a[2])), "r"(__float_as_uint(a[3])),
          "r"(__float_as_uint(b[0])), "r"(__float_as_uint(b[1])));
}

// ====================== GEMM (TMA + mma.sync fp16) =========================
// CTA 128x256, warp tile 64x64, BK=64 fp16 (=128B SW128 rows), GS=4
#define GBM 128
#define GBN 256
#define GBK 64
#define GS  4
#define STAGE_A_BYTES (GBM * GBK * 2)                 // 16384
#define STAGE_B_BYTES (GBN * GBK * 2)                 // 32768
#define STAGE_BYTES   (STAGE_A_BYTES + STAGE_B_BYTES) // 49152
#define SMEM_A_OFF(s) (1024 + (s) * STAGE_BYTES)
#define SMEM_B_OFF(s) (SMEM_A_OFF(s) + STAGE_A_BYTES)
#define GEMM_SMEM_TOTAL (1024 + GS * STAGE_BYTES)     // 197632

// OUT_HALF: write __half (mid); else float (kqv / final)
template <bool OUT_HALF, bool DO_BIAS, bool DO_RELU, bool DO_RESID, bool DO_TF32OUT>
__global__ __launch_bounds__(288, 1) void gemm_f16_kernel(
    const __grid_constant__ CUtensorMap tmA,
    const __grid_constant__ CUtensorMap tmB,
    const float* __restrict__ bias,
    const float* __restrict__ resid,
    void*        __restrict__ Cv,
    int N, int K)
{
    extern __shared__ __align__(1024) char smem[];
    const uint32_t sb = smem_u32(smem);
    const int tid  = threadIdx.x;
    const int wid  = tid >> 5;
    const int lane = tid & 31;
    const int m0 = blockIdx.y * GBM;
    const int n0 = blockIdx.x * GBN;

    if (tid == 0) {
        #pragma unroll
        for (int s = 0; s < GS; s++) {
            MBARRIER_INIT(sb + 8 * s, 1);
            MBARRIER_INIT(sb + 64 + 8 * s, 8);
        }
    }
    __syncthreads();

    const int nk = K / GBK;

    if (wid == 8) {
        if (lane == 0) {
            int s = 0, eph = 0;   // eph = post-wrap phase; previous round = eph^1
            for (int j = 0; j < nk; j++) {
                if (j >= GS) MBARRIER_WAIT_PARITY_RELAXED(sb + 64 + 8 * s, eph ^ 1);
                MBARRIER_EXPECT_TX(sb + 8 * s, STAGE_BYTES);
                TMA2D(sb + SMEM_A_OFF(s), &tmA, j * GBK, m0, sb + 8 * s);
                TMA2D(sb + SMEM_B_OFF(s), &tmB, j * GBK, n0, sb + 8 * s);
                if (++s == GS) { s = 0; eph ^= 1; }
            }
        }
        return;
    }

    // consumers 0..7: warp tile 64(m) x 64(n)
    const int warp_m = wid >> 2;   // 0..1
    const int warp_n = wid & 3;    // 0..3
    const int g   = lane >> 2;     // 0..7
    const int tig = lane & 3;      // 0..3

    float acc[4][8][4];
    #pragma unroll
    for (int i = 0; i < 4; i++)
        #pragma unroll
        for (int j = 0; j < 8; j++)
            #pragma unroll
            for (int q = 0; q < 4; q++) acc[i][j][q] = 0.f;

    // rows: a row = warp_m*64 + mf*16 + g ; b row = warp_n*64 + nf*8 + g
    // (row & 7) == g for all tiles -> single swizzle xor
    const uint32_t xr = (uint32_t)g << 4;
    uint32_t aRowOff[4];
    #pragma unroll
    for (int mf = 0; mf < 4; mf++)
        aRowOff[mf] = (uint32_t)(warp_m * 64 + mf * 16 + g) * 128;
    uint32_t bRowOff[8];
    #pragma unroll
    for (int nf = 0; nf < 8; nf++)
        bRowOff[nf] = (uint32_t)(warp_n * 64 + nf * 8 + g) * 128;

    int s = 0, ph = 0;
    for (int i = 0; i < nk; i++) {
        MBARRIER_WAIT_PARITY(sb + 8 * s, ph);

        const uint32_t aB = sb + SMEM_A_OFF(s);
        const uint32_t bB = sb + SMEM_B_OFF(s);

        #pragma unroll
        for (int kf = 0; kf < 4; kf++) {          // 4 x k16 = BK 64
            const uint32_t k0b = (uint32_t)(kf * 32 + tig * 4);  // k=2*tig pair
            const uint32_t k1b = k0b + 16;                        // k+8 pair
            uint32_t a[4][4];
            #pragma unroll
            for (int mf = 0; mf < 4; mf++) {
                a[mf][0] = lds_u32(aB + aRowOff[mf] + (k0b ^ xr));
                a[mf][1] = lds_u32(aB + aRowOff[mf] + 1024 + (k0b ^ xr));
                a[mf][2] = lds_u32(aB + aRowOff[mf] + (k1b ^ xr));
                a[mf][3] = lds_u32(aB + aRowOff[mf] + 1024 + (k1b ^ xr));
            }
            uint32_t b[8][2];
            #pragma unroll
            for (int nf = 0; nf < 8; nf++) {
                b[nf][0] = lds_u32(bB + bRowOff[nf] + (k0b ^ xr));
                b[nf][1] = lds_u32(bB + bRowOff[nf] + (k1b ^ xr));
            }
            #pragma unroll
            for (int mf = 0; mf < 4; mf++)
                #pragma unroll
                for (int nf = 0; nf < 8; nf++)
                    mma_f16(acc[mf][nf], a[mf], b[nf]);
        }

        __syncwarp();
        if (lane == 0) MBARRIER_ARRIVE(sb + 64 + 8 * s);
        if (++s == GS) { s = 0; ph ^= 1; }
    }

    #pragma unroll
    for (int mf = 0; mf < 4; mf++) {
        const int row0 = m0 + warp_m * 64 + mf * 16 + g;
        #pragma unroll
        for (int nf = 0; nf < 8; nf++) {
            const int col = n0 + warp_n * 64 + nf * 8 + 2 * tig;
            float2 v0 = make_float2(acc[mf][nf][0], acc[mf][nf][1]);
            float2 v1 = make_float2(acc[mf][nf][2], acc[mf][nf][3]);
            if (DO_BIAS) {
                float2 bb = *(const float2*)(bias + col);
                v0.x += bb.x; v0.y += bb.y; v1.x += bb.x; v1.y += bb.y;
            }
            if (DO_RELU) {
                v0.x = fmaxf(v0.x, 0.f); v0.y = fmaxf(v0.y, 0.f);
                v1.x = fmaxf(v1.x, 0.f); v1.y = fmaxf(v1.y, 0.f);
            }
            if (OUT_HALF) {
                __half* C = (__half*)Cv;
                *(__half2*)(C + (size_t)row0 * N + col)       = __floats2half2_rn(v0.x, v0.y);
                *(__half2*)(C + (size_t)(row0 + 8) * N + col) = __floats2half2_rn(v1.x, v1.y);
            } else {
                float* C = (float*)Cv;
                if (DO_TF32OUT) {
                    v0.x = tf32r(v0.x); v0.y = tf32r(v0.y);
                    v1.x = tf32r(v1.x); v1.y = tf32r(v1.y);
                }
                if (DO_RESID) {
                    float2 r0 = *(const float2*)(resid + (size_t)row0 * N + col);
                    float2 r1 = *(const float2*)(resid + (size_t)(row0 + 8) * N + col);
                    v0.x += r0.x; v0.y += r0.y; v1.x += r1.x; v1.y += r1.y;
                }
                *(float2*)(C + (size_t)row0 * N + col)       = v0;
                *(float2*)(C + (size_t)(row0 + 8) * N + col) = v1;
            }
        }
    }
}

// ====================== transpose [R,C] fp32 -> [C,R] fp16 ================
__global__ __launch_bounds__(256) void transpose_kernel(
    const float* __restrict__ in, __half* __restrict__ out, int R, int C)
{
    __shared__ float t[32][33];
    const int bx = blockIdx.x * 32, by = blockIdx.y * 32;
    const int x = threadIdx.x, y = threadIdx.y;
    #pragma unroll
    for (int i = 0; i < 32; i += 8)
        t[y + i][x] = in[(size_t)(by + y + i) * C + bx + x];
    __syncthreads();
    #pragma unroll
    for (int i = 0; i < 32; i += 8)
        out[(size_t)(bx + y + i) * R + by + x] = __float2half_rn(t[x][y + i]);
}

// ====================== LayerNorm (fp16 output for GEMM input) ============
template <bool FUSE_ADD>
__global__ __launch_bounds__(256) void ln_kernel(
    const float* __restrict__ x,
    const float* __restrict__ addend,
    float*       __restrict__ resid_out,
    const float* __restrict__ gamma,
    const float* __restrict__ beta,
    __half*      __restrict__ out)
{
    const int row = blockIdx.x;
    const int t   = threadIdx.x;
    const size_t base = (size_t)row * EMB;

    float4 v = *(const float4*)(x + base + t * 4);
    if (FUSE_ADD) {
        float4 a = *(const float4*)(addend + base + t * 4);
        v.x += a.x; v.y += a.y; v.z += a.z; v.w += a.w;
        *(float4*)(resid_out + base + t * 4) = v;
    }
    float s  = v.x + v.y + v.z + v.w;
    float ss = v.x*v.x + v.y*v.y + v.z*v.z + v.w*v.w;

    #pragma unroll
    for (int off = 16; off; off >>= 1) {
        s  += __shfl_down_sync(0xffffffffu, s,  off);
        ss += __shfl_down_sync(0xffffffffu, ss, off);
    }
    __shared__ float rs[8], rss[8];
    const int warp = t >> 5, lane = t & 31;
    if (lane == 0) { rs[warp] = s; rss[warp] = ss; }
    __syncthreads();
    if (t == 0) {
        float a = 0.f, b = 0.f;
        #pragma unroll
        for (int i = 0; i < 8; i++) { a += rs[i]; b += rss[i]; }
        rs[0] = a; rss[0] = b;
    }
    __syncthreads();
    const float mu  = rs[0] * (1.0f / EMB);
    const float var = rss[0] * (1.0f / EMB) - mu * mu;
    const float inv = rsqrtf(var + 1e-5f);

    float4 g  = *(const float4*)(gamma + t * 4);
    float4 b4 = *(const float4*)(beta  + t * 4);
    __half2 h0 = __floats2half2_rn((v.x - mu) * inv * g.x + b4.x,
                                   (v.y - mu) * inv * g.y + b4.y);
    __half2 h1 = __floats2half2_rn((v.z - mu) * inv * g.z + b4.z,
                                   (v.w - mu) * inv * g.w + b4.w);
    uint2 st;
    st.x = *(uint32_t*)&h0;
    st.y = *(uint32_t*)&h1;
    *(uint2*)(out + base + t * 4) = st;
}

// ====================== Flash attention (tensor cores, unchanged) =========
#define AT_KOFF(s) (17408 + (s) * 17408)
#define AT_VOFF(s) (52224 + (s) * 18432)
#define ATTN_SMEM  89088

__device__ __forceinline__ void load_kv(uint32_t sb, const float* __restrict__ kqv,
                                        int b, int h, int t, int buf, int tid)
{
    const float* base = kqv + ((size_t)(b * SEQ + t * 64)) * 3072 + h * 64;
    const uint32_t kd = sb + AT_KOFF(buf);
    const uint32_t vd = sb + AT_VOFF(buf);
    #pragma unroll
    for (int i = 0; i < 8; i++) {
        const int idx = tid + i * 128;
        const int row = idx >> 4, c4 = idx & 15;
        cpasync16(kd + (uint32_t)(row * 68 + c4 * 4) * 4, base + (size_t)row * 3072 + c4 * 4);
        cpasync16(vd + (uint32_t)(row * 72 + c4 * 4) * 4, base + (size_t)row * 3072 + 2048 + c4 * 4);
    }
}

__global__ __launch_bounds__(128) void attn_kernel(
    const float* __restrict__ kqv, float* __restrict__ out)
{
    extern __shared__ __align__(16) char asmem[];
    const uint32_t sb = smem_u32(asmem);
    const int bx = (int)gridDim.x - 1 - (int)blockIdx.x;   // longest-first
    const int h = blockIdx.y, b = blockIdx.z;
    const int tid = threadIdx.x, w = tid >> 5, lane = tid & 31;
    const int tig = lane & 3, grp = lane >> 2;
    const float LOG2E = 1.4426950408889634f;
    const float slope2 = exp2f(-0.5f * (float)(h + 1)) * LOG2E;
    const int q0 = bx * 64;
    const int nt = bx + 1;

    {
        const float* qb = kqv + ((size_t)(b * SEQ + q0)) * 3072 + 1024 + h * 64;
        #pragma unroll
        for (int i = 0; i < 8; i++) {
            const int idx = tid + i * 128, row = idx >> 4, c4 = idx & 15;
            cpasync16(sb + (uint32_t)(row * 68 + c4 * 4) * 4, qb + (size_t)row * 3072 + c4 * 4);
        }
    }
    load_kv(sb, kqv, b, h, 0, 0, tid);
    CP_COMMIT();
    if (nt > 1) { load_kv(sb, kqv, b, h, 1, 1, tid); CP_COMMIT(); CP_WAIT(1); }
    else        { CP_WAIT(0); }
    __syncthreads();

    const float* Qs = (const float*)asmem;
    float qa[8][4];
    {
        const int r0 = w * 16 + grp;
        const float qs = LOG2E / 32.0f;
        #pragma unroll
        for (int kk = 0; kk < 8; kk++) {
            const int c = kk * 8 + tig;
            qa[kk][0] = Qs[r0 * 68 + c] * qs;
            qa[kk][1] = Qs[(r0 + 8) * 68 + c] * qs;
            qa[kk][2] = Qs[r0 * 68 + c + 4] * qs;
            qa[kk][3] = Qs[(r0 + 8) * 68 + c + 4] * qs;
        }
    }

    float o[8][4];
    #pragma unroll
    for (int nf = 0; nf < 8; nf++) { o[nf][0] = o[nf][1] = o[nf][2] = o[nf][3] = 0.f; }
    float m0 = -INFINITY, m1 = -INFINITY, l0 = 0.f, l1 = 0.f;
    const int qrow = q0 + w * 16 + grp;

    for (int t = 0; t < nt; t++) {
        const float* Ks = (const float*)(asmem + AT_KOFF(t & 1));
        const float* Vs = (const float*)(asmem + AT_VOFF(t & 1));
        const bool diag = (t == nt - 1);

        float s[8][4];
        #pragma unroll
        for (int nf = 0; nf < 8; nf++) { s[nf][0] = s[nf][1] = s[nf][2] = s[nf][3] = 0.f; }
        #pragma unroll
        for (int kk = 0; kk < 8; kk++) {
            #pragma unroll
            for (int nf = 0; nf < 8; nf++) {
                float bf[2];
                bf[0] = Ks[(nf * 8 + grp) * 68 + kk * 8 + tig];
                bf[1] = Ks[(nf * 8 + grp) * 68 + kk * 8 + tig + 4];
                mma_tf32(s[nf], qa[kk], bf);
            }
        }

        float mx0 = -INFINITY, mx1 = -INFINITY;
        #pragma unroll
        for (int nf = 0; nf < 8; nf++) {
            #pragma unroll
            for (int e = 0; e < 2; e++) {
                const int key = t * 64 + nf * 8 + 2 * tig + e;
                const float r0f = (float)(key - qrow);
                const float r1f = r0f - 8.0f;
                float v0 = s[nf][e]     + slope2 * r0f;
                float v1 = s[nf][e + 2] + slope2 * r1f;
                if (diag) {
                    if (r0f > 0.f) v0 = -1e30f;
                    if (r1f > 0.f) v1 = -1e30f;
                }
                s[nf][e] = v0; s[nf][e + 2] = v1;
                mx0 = fmaxf(mx0, v0); mx1 = fmaxf(mx1, v1);
            }
        }
        mx0 = fmaxf(mx0, __shfl_xor_sync(~0u, mx0, 1));
        mx0 = fmaxf(mx0, __shfl_xor_sync(~0u, mx0, 2));
        mx1 = fmaxf(mx1, __shfl_xor_sync(~0u, mx1, 1));
        mx1 = fmaxf(mx1, __shfl_xor_sync(~0u, mx1, 2));
        const float mn0 = fmaxf(m0, mx0), mn1 = fmaxf(m1, mx1);
        const float c0 = ex2(m0 - mn0), c1 = ex2(m1 - mn1);
        m0 = mn0; m1 = mn1;

        float rs0 = 0.f, rs1 = 0.f;
        #pragma unroll
        for (int nf = 0; nf < 8; nf++) {
            #pragma unroll
            for (int e = 0; e < 2; e++) {
                const float p0 = ex2(s[nf][e] - m0);
                const float p1 = ex2(s[nf][e + 2] - m1);
                s[nf][e] = p0; s[nf][e + 2] = p1;
                rs0 += p0; rs1 += p1;
            }
        }
        rs0 += __shfl_xor_sync(~0u, rs0, 1); rs0 += __shfl_xor_sync(~0u, rs0, 2);
        rs1 += __shfl_xor_sync(~0u, rs1, 1); rs1 += __shfl_xor_sync(~0u, rs1, 2);
        l0 = l0 * c0 + rs0; l1 = l1 * c1 + rs1;

        #pragma unroll
        for (int nf = 0; nf < 8; nf++) {
            o[nf][0] *= c0; o[nf][1] *= c0; o[nf][2] *= c1; o[nf][3] *= c1;
        }

        const int s1 = (lane & ~3) | (tig >> 1);
        const int s2 = s1 + 2;
        #pragma unroll
        for (int kk = 0; kk < 8; kk++) {
            const float v0 = __shfl_sync(~0u, s[kk][0], s1);
            const float v1 = __shfl_sync(~0u, s[kk][1], s1);
            const float v2 = __shfl_sync(~0u, s[kk][2], s1);
            const float v3 = __shfl_sync(~0u, s[kk][3], s1);
            const float w0 = __shfl_sync(~0u, s[kk][0], s2);
            const float w1 = __shfl_sync(~0u, s[kk][1], s2);
            const float w2 = __shfl_sync(~0u, s[kk][2], s2);
            const float w3 = __shfl_sync(~0u, s[kk][3], s2);
            float pa[4];
            pa[0] = (tig & 1) ? v1 : v0;
            pa[1] = (tig & 1) ? v3 : v2;
            pa[2] = (tig & 1) ? w1 : w0;
            pa[3] = (tig & 1) ? w3 : w2;
            #pragma unroll
            for (int nf = 0; nf < 8; nf++) {
                float bf[2];
                bf[0] = Vs[(kk * 8 + tig) * 72 + nf * 8 + grp];
                bf[1] = Vs[(kk * 8 + tig + 4) * 72 + nf * 8 + grp];
                mma_tf32(o[nf], pa, bf);
            }
        }

        __syncthreads();
        if (t + 1 < nt) {
            if (t + 2 < nt) { load_kv(sb, kqv, b, h, t + 2, t & 1, tid); CP_COMMIT(); CP_WAIT(1); }
            else            { CP_WAIT(0); }
            __syncthreads();
        }
    }

    const float il0 = 1.0f / l0, il1 = 1.0f / l1;
    float* op = out + ((size_t)(b * SEQ + qrow)) * EMB + h * 64;
    #pragma unroll
    for (int nf = 0; nf < 8; nf++) {
        const int col = nf * 8 + 2 * tig;
        float2 u0 = make_float2(o[nf][0] * il0, o[nf][1] * il0);
        float2 u1 = make_float2(o[nf][2] * il1, o[nf][3] * il1);
        *(float2*)(op + col) = u0;
        *(float2*)(op + (size_t)8 * EMB + col) = u1;
    }
}

// ====================== host: tensor maps ==================================
typedef CUresult (*EncodeTiledFn)(
    CUtensorMap*, CUtensorMapDataType, cuuint32_t, void*,
    const cuuint64_t*, const cuuint64_t*, const cuuint32_t*, const cuuint32_t*,
    CUtensorMapInterleave, CUtensorMapSwizzle, CUtensorMapL2promotion,
    CUtensorMapFloatOOBfill);

static void make_map_f16(EncodeTiledFn enc, CUtensorMap* m, const __half* p,
                         int K, int rows, int boxRows) {
    cuuint64_t dims[2]    = {(cuuint64_t)K, (cuuint64_t)rows};
    cuuint64_t strides[1] = {(cuuint64_t)K * 2};
    cuuint32_t box[2]     = {(cuuint32_t)GBK, (cuuint32_t)boxRows};
    cuuint32_t es[2]      = {1, 1};
    enc(m, CU_TENSOR_MAP_DATA_TYPE_FLOAT16, 2, (void*)p, dims, strides, box, es,
        CU_TENSOR_MAP_INTERLEAVE_NONE, CU_TENSOR_MAP_SWIZZLE_128B,
        CU_TENSOR_MAP_L2_PROMOTION_L2_128B, CU_TENSOR_MAP_FLOAT_OOB_FILL_NONE);
}

// ====================== driver =============================================
extern "C" void kernel_launch(void* const* d_in, const int* in_sizes, int n_in,
                              void* d_out, int out_size)
{
    const float* x     = (const float*)d_in[0];
    const float* w_kqv = (const float*)d_in[1];
    const float* ln1_g = (const float*)d_in[2];
    const float* ln1_b = (const float*)d_in[3];
    const float* ln2_g = (const float*)d_in[4];
    const float* ln2_b = (const float*)d_in[5];
    const float* w1    = (const float*)d_in[6];
    const float* b1    = (const float*)d_in[7];
    const float* w2    = (const float*)d_in[8];
    const float* b2    = (const float*)d_in[9];
    float* out = (float*)d_out;

    __half *xn, *hbuf, *mid, *wkqvT, *w1T, *w2T;
    float *kqv, *attn;
    cudaGetSymbolAddress((void**)&xn,    g_xn);
    cudaGetSymbolAddress((void**)&kqv,   g_kqv);
    cudaGetSymbolAddress((void**)&attn,  g_attn);
    cudaGetSymbolAddress((void**)&hbuf,  g_h);
    cudaGetSymbolAddress((void**)&mid,   g_mid);
    cudaGetSymbolAddress((void**)&wkqvT, g_wkqvT);
    cudaGetSymbolAddress((void**)&w1T,   g_w1T);
    cudaGetSymbolAddress((void**)&w2T,   g_w2T);

    EncodeTiledFn enc = nullptr;
    {
        cudaDriverEntryPointQueryResult st;
        cudaGetDriverEntryPointByVersion("cuTensorMapEncodeTiled", (void**)&enc,
                                         12000, cudaEnableDefault, &st);
    }

    alignas(64) CUtensorMap mA1, mB1, mA2, mB2, mA3, mB3;
    make_map_f16(enc, &mA1, xn,    EMB, ROWS,    GBM);
    make_map_f16(enc, &mB1, wkqvT, EMB, 3 * EMB, GBN);
    make_map_f16(enc, &mA2, hbuf,  EMB, ROWS,    GBM);
    make_map_f16(enc, &mB2, w1T,   EMB, DFF,     GBN);
    make_map_f16(enc, &mA3, mid,   DFF, ROWS,    GBM);
    make_map_f16(enc, &mB3, w2T,   DFF, EMB,     GBN);

    cudaFuncSetAttribute(gemm_f16_kernel<false, false, false, false, true>,
                         cudaFuncAttributeMaxDynamicSharedMemorySize, GEMM_SMEM_TOTAL);
    cudaFuncSetAttribute(gemm_f16_kernel<true, true, true, false, false>,
                         cudaFuncAttributeMaxDynamicSharedMemorySize, GEMM_SMEM_TOTAL);
    cudaFuncSetAttribute(gemm_f16_kernel<false, true, false, true, false>,
                         cudaFuncAttributeMaxDynamicSharedMemorySize, GEMM_SMEM_TOTAL);
    cudaFuncSetAttribute(attn_kernel,
                         cudaFuncAttributeMaxDynamicSharedMemorySize, ATTN_SMEM);

    // 0) weight transposes -> fp16 [N,K]
    transpose_kernel<<<dim3(3 * EMB / 32, EMB / 32), dim3(32, 8)>>>(w_kqv, wkqvT, EMB, 3 * EMB);
    transpose_kernel<<<dim3(DFF / 32, EMB / 32), dim3(32, 8)>>>(w1, w1T, EMB, DFF);
    transpose_kernel<<<dim3(EMB / 32, DFF / 32), dim3(32, 8)>>>(w2, w2T, DFF, EMB);

    // 1) LN1 -> fp16
    ln_kernel<false><<<ROWS, 256>>>(x, nullptr, nullptr, ln1_g, ln1_b, xn);

    // 2) kqv = xn @ w_kqv  (fp32 out, tf32-rounded for attention)
    gemm_f16_kernel<false, false, false, false, true>
        <<<dim3(3 * EMB / GBN, ROWS / GBM), 288, GEMM_SMEM_TOTAL>>>(
            mA1, mB1, nullptr, nullptr, kqv, 3 * EMB, EMB);

    // 3) attention (fp32/tf32)
    attn_kernel<<<dim3(SEQ / 64, NH, BATCH), 128, ATTN_SMEM>>>(kqv, attn);

    // 4) x1 = x + attn (-> out), h = LN2(x1) -> fp16
    ln_kernel<true><<<ROWS, 256>>>(x, attn, out, ln2_g, ln2_b, hbuf);

    // 5) mid = relu(h @ w1 + b1) -> fp16
    gemm_f16_kernel<true, true, true, false, false>
        <<<dim3(DFF / GBN, ROWS / GBM), 288, GEMM_SMEM_TOTAL>>>(
            mA2, mB2, b1, nullptr, mid, DFF, EMB);

    // 6) out = x1 + mid @ w2 + b2  (fp32 out + residual)
    gemm_f16_kernel<false, true, false, true, false>
        <<<dim3(EMB / GBN, ROWS / GBM), 288, GEMM_SMEM_TOTAL>>>(
            mA3, mB3, b2, out, out, EMB, DFF);

    (void)in_sizes; (void)n_in; (void)out_size;
}

// round 11
// speedup vs baseline: 1.7116x; 1.1779x over previous
#include <cuda_runtime.h>
#include <cuda.h>
#include <cuda_fp16.h>
#include <stdint.h>
#include <math.h>

#define BATCH 2
#define SEQ   2048
#define EMB   1024
#define NH    16
#define HD    64
#define DFF   4096
#define ROWS  (BATCH*SEQ)   // 4096

// ---------------- scratch (device globals; no allocation) ----------------
__device__ __align__(128) __half g_xn   [ROWS * EMB];
__device__ __align__(128) __half g_kqv  [ROWS * 3 * EMB];
__device__ __align__(128) float  g_attn [ROWS * EMB];
__device__ __align__(128) __half g_h    [ROWS * EMB];
__device__ __align__(128) __half g_mid  [ROWS * DFF];
__device__ __align__(128) __half g_wkqvT[3 * EMB * EMB];
__device__ __align__(128) __half g_w1T  [DFF * EMB];
__device__ __align__(128) __half g_w2T  [EMB * DFF];

// ====================== PTX helpers ========================================
__device__ __forceinline__ uint32_t smem_u32(const void* p) {
    uint32_t a;
    asm("{ .reg .u64 t; cvta.to.shared.u64 t, %1; cvt.u32.u64 %0, t; }"
        : "=r"(a) : "l"(p));
    return a;
}

__device__ __forceinline__ float ex2(float x) {
    float y;
    asm("ex2.approx.f32 %0, %1;" : "=f"(y) : "f"(x));
    return y;
}

#define MBARRIER_INIT(addr, cnt) \
    asm volatile("mbarrier.init.shared.b64 [%0], %1;" :: "r"((uint32_t)(addr)), "r"((uint32_t)(cnt)) : "memory")

#define MBARRIER_ARRIVE(addr) \
    asm volatile("mbarrier.arrive.shared.b64 _, [%0];" :: "r"((uint32_t)(addr)) : "memory")

#define MBARRIER_EXPECT_TX(addr, bytes) \
    asm volatile("mbarrier.arrive.expect_tx.shared.b64 _, [%0], %1;" :: "r"((uint32_t)(addr)), "r"((uint32_t)(bytes)) : "memory")

#define MBARRIER_WAIT_PARITY(addr, ph) do { \
    uint32_t _m = (uint32_t)(addr); uint32_t _p = (uint32_t)(ph); uint32_t _d; \
    asm volatile("{\n\t.reg .pred p;\n\t" \
        "mbarrier.try_wait.parity.acquire.cta.shared::cta.b64 p, [%1], %2;\n\t" \
        "selp.b32 %0, 1, 0, p;\n\t}" : "=r"(_d) : "r"(_m), "r"(_p) : "memory"); \
    if (!_d) { \
        asm volatile("{\n\t.reg .pred P1;\n\t" \
            "WL_%=:\n\t" \
            "mbarrier.try_wait.parity.acquire.cta.shared::cta.b64 P1, [%0], %1, 0x989680;\n\t" \
            "@P1 bra.uni WD_%=;\n\t" \
            "bra.uni WL_%=;\n\t" \
            "WD_%=:\n\t}" :: "r"(_m), "r"(_p) : "memory"); \
    } \
} while (0)

#define MBARRIER_WAIT_PARITY_RELAXED(addr, ph) do { \
    uint32_t _m = (uint32_t)(addr); uint32_t _p = (uint32_t)(ph); uint32_t _d; \
    asm volatile("{\n\t.reg .pred p;\n\t" \
        "mbarrier.try_wait.parity.relaxed.cta.shared::cta.b64 p, [%1], %2, 0x989680;\n\t" \
        "selp.b32 %0, 1, 0, p;\n\t}" : "=r"(_d) : "r"(_m), "r"(_p) : "memory"); \
    if (!_d) { \
        asm volatile("{\n\t.reg .pred P1;\n\t" \
            "WL_%=:\n\t" \
            "mbarrier.try_wait.parity.relaxed.cta.shared::cta.b64 P1, [%0], %1, 0x989680;\n\t" \
            "@P1 bra.uni WD_%=;\n\t" \
            "bra.uni WL_%=;\n\t" \
            "WD_%=:\n\t}" :: "r"(_m), "r"(_p) : "memory"); \
    } \
} while (0)

#define TMA2D(smemaddr, mapptr, cx, cy, mbar) \
    asm volatile("cp.async.bulk.tensor.2d.shared::cta.global.tile.mbarrier::complete_tx::bytes " \
        "[%0], [%1, {%2, %3}], [%4];" \
        :: "r"((uint32_t)(smemaddr)), "l"(mapptr), "r"((int)(cx)), "r"((int)(cy)), \
           "r"((uint32_t)(mbar)) : "memory")

__device__ __forceinline__ uint32_t lds_u32(uint32_t addr) {
    uint32_t v;
    asm volatile("ld.shared.b32 %0, [%1];" : "=r"(v) : "r"(addr));
    return v;
}
__device__ __forceinline__ void sts_u32(uint32_t addr, uint32_t v) {
    asm volatile("st.shared.b32 [%0], %1;" :: "r"(addr), "r"(v) : "memory");
}

__device__ __forceinline__ void cpasync16(uint32_t dst, const void* src) {
    asm volatile("cp.async.cg.shared.global [%0], [%1], 16;" :: "r"(dst), "l"(src));
}
#define CP_COMMIT() asm volatile("cp.async.commit_group;" ::: "memory")
#define CP_WAIT(n)  asm volatile("cp.async.wait_group %0;" :: "n"(n) : "memory")

// fp16 mma m16n8k16, fp32 accumulate
__device__ __forceinline__ void mma_f16(float* c, const uint32_t* a, const uint32_t* b) {
    asm volatile(
        "mma.sync.aligned.m16n8k16.row.col.f32.f16.f16.f32 "
        "{%0,%1,%2,%3}, {%4,%5,%6,%7}, {%8,%9}, {%0,%1,%2,%3};"
        : "+f"(c[0]), "+f"(c[1]), "+f"(c[2]), "+f"(c[3])
        : "r"(a[0]), "r"(a[1]), "r"(a[2]), "r"(a[3]),
          "r"(b[0]), "r"(b[1]));
}

__device__ __forceinline__ uint32_t pack_h2(float x, float y) {
    __half2 h = __floats2half2_rn(x, y);
    return *(uint32_t*)&h;
}

// ====================== GEMM (TMA + mma.sync fp16) =========================
#define GBM 128
#define GBN 256
#define GBK 64
#define GS  4
#define STAGE_A_BYTES (GBM * GBK * 2)
#define STAGE_B_BYTES (GBN * GBK * 2)
#define STAGE_BYTES   (STAGE_A_BYTES + STAGE_B_BYTES)
#define SMEM_A_OFF(s) (1024 + (s) * STAGE_BYTES)
#define SMEM_B_OFF(s) (SMEM_A_OFF(s) + STAGE_A_BYTES)
#define GEMM_SMEM_TOTAL (1024 + GS * STAGE_BYTES)

template <bool OUT_HALF, bool DO_BIAS, bool DO_RELU, bool DO_RESID>
__global__ __launch_bounds__(288, 1) void gemm_f16_kernel(
    const __grid_constant__ CUtensorMap tmA,
    const __grid_constant__ CUtensorMap tmB,
    const float* __restrict__ bias,
    const float* __restrict__ resid,
    void*        __restrict__ Cv,
    int N, int K)
{
    extern __shared__ __align__(1024) char smem[];
    const uint32_t sb = smem_u32(smem);
    const int tid  = threadIdx.x;
    const int wid  = tid >> 5;
    const int lane = tid & 31;
    const int m0 = blockIdx.y * GBM;
    const int n0 = blockIdx.x * GBN;

    if (tid == 0) {
        #pragma unroll
        for (int s = 0; s < GS; s++) {
            MBARRIER_INIT(sb + 8 * s, 1);
            MBARRIER_INIT(sb + 64 + 8 * s, 8);
        }
    }
    __syncthreads();

    const int nk = K / GBK;

    if (wid == 8) {
        if (lane == 0) {
            int s = 0, eph = 0;
            for (int j = 0; j < nk; j++) {
                if (j >= GS) MBARRIER_WAIT_PARITY_RELAXED(sb + 64 + 8 * s, eph ^ 1);
                MBARRIER_EXPECT_TX(sb + 8 * s, STAGE_BYTES);
                TMA2D(sb + SMEM_A_OFF(s), &tmA, j * GBK, m0, sb + 8 * s);
                TMA2D(sb + SMEM_B_OFF(s), &tmB, j * GBK, n0, sb + 8 * s);
                if (++s == GS) { s = 0; eph ^= 1; }
            }
        }
        return;
    }

    const int warp_m = wid >> 2;
    const int warp_n = wid & 3;
    const int g   = lane >> 2;
    const int tig = lane & 3;

    float acc[4][8][4];
    #pragma unroll
    for (int i = 0; i < 4; i++)
        #pragma unroll
        for (int j = 0; j < 8; j++)
            #pragma unroll
            for (int q = 0; q < 4; q++) acc[i][j][q] = 0.f;

    const uint32_t xr = (uint32_t)g << 4;
    uint32_t aRowOff[4];
    #pragma unroll
    for (int mf = 0; mf < 4; mf++)
        aRowOff[mf] = (uint32_t)(warp_m * 64 + mf * 16 + g) * 128;
    uint32_t bRowOff[8];
    #pragma unroll
    for (int nf = 0; nf < 8; nf++)
        bRowOff[nf] = (uint32_t)(warp_n * 64 + nf * 8 + g) * 128;

    int s = 0, ph = 0;
    for (int i = 0; i < nk; i++) {
        MBARRIER_WAIT_PARITY(sb + 8 * s, ph);

        const uint32_t aB = sb + SMEM_A_OFF(s);
        const uint32_t bB = sb + SMEM_B_OFF(s);

        #pragma unroll
        for (int kf = 0; kf < 4; kf++) {
            const uint32_t k0b = (uint32_t)(kf * 32 + tig * 4);
            const uint32_t k1b = k0b + 16;
            uint32_t a[4][4];
            #pragma unroll
            for (int mf = 0; mf < 4; mf++) {
                a[mf][0] = lds_u32(aB + aRowOff[mf] + (k0b ^ xr));
                a[mf][1] = lds_u32(aB + aRowOff[mf] + 1024 + (k0b ^ xr));
                a[mf][2] = lds_u32(aB + aRowOff[mf] + (k1b ^ xr));
                a[mf][3] = lds_u32(aB + aRowOff[mf] + 1024 + (k1b ^ xr));
            }
            uint32_t b[8][2];
            #pragma unroll
            for (int nf = 0; nf < 8; nf++) {
                b[nf][0] = lds_u32(bB + bRowOff[nf] + (k0b ^ xr));
                b[nf][1] = lds_u32(bB + bRowOff[nf] + (k1b ^ xr));
            }
            #pragma unroll
            for (int mf = 0; mf < 4; mf++)
                #pragma unroll
                for (int nf = 0; nf < 8; nf++)
                    mma_f16(acc[mf][nf], a[mf], b[nf]);
        }

        __syncwarp();
        if (lane == 0) MBARRIER_ARRIVE(sb + 64 + 8 * s);
        if (++s == GS) { s = 0; ph ^= 1; }
    }

    #pragma unroll
    for (int mf = 0; mf < 4; mf++) {
        const int row0 = m0 + warp_m * 64 + mf * 16 + g;
        #pragma unroll
        for (int nf = 0; nf < 8; nf++) {
            const int col = n0 + warp_n * 64 + nf * 8 + 2 * tig;
            float2 v0 = make_float2(acc[mf][nf][0], acc[mf][nf][1]);
            float2 v1 = make_float2(acc[mf][nf][2], acc[mf][nf][3]);
            if (DO_BIAS) {
                float2 bb = *(const float2*)(bias + col);
                v0.x += bb.x; v0.y += bb.y; v1.x += bb.x; v1.y += bb.y;
            }
            if (DO_RELU) {
                v0.x = fmaxf(v0.x, 0.f); v0.y = fmaxf(v0.y, 0.f);
                v1.x = fmaxf(v1.x, 0.f); v1.y = fmaxf(v1.y, 0.f);
            }
            if (OUT_HALF) {
                __half* C = (__half*)Cv;
                *(__half2*)(C + (size_t)row0 * N + col)       = __floats2half2_rn(v0.x, v0.y);
                *(__half2*)(C + (size_t)(row0 + 8) * N + col) = __floats2half2_rn(v1.x, v1.y);
            } else {
                float* C = (float*)Cv;
                if (DO_RESID) {
                    float2 r0 = *(const float2*)(resid + (size_t)row0 * N + col);
                    float2 r1 = *(const float2*)(resid + (size_t)(row0 + 8) * N + col);
                    v0.x += r0.x; v0.y += r0.y; v1.x += r1.x; v1.y += r1.y;
                }
                *(float2*)(C + (size_t)row0 * N + col)       = v0;
                *(float2*)(C + (size_t)(row0 + 8) * N + col) = v1;
            }
        }
    }
}

// ====================== transpose [R,C] fp32 -> [C,R] fp16 ================
__global__ __launch_bounds__(256) void transpose_kernel(
    const float* __restrict__ in, __half* __restrict__ out, int R, int C)
{
    __shared__ float t[32][33];
    const int bx = blockIdx.x * 32, by = blockIdx.y * 32;
    const int x = threadIdx.x, y = threadIdx.y;
    #pragma unroll
    for (int i = 0; i < 32; i += 8)
        t[y + i][x] = in[(size_t)(by + y + i) * C + bx + x];
    __syncthreads();
    #pragma unroll
    for (int i = 0; i < 32; i += 8)
        out[(size_t)(bx + y + i) * R + by + x] = __float2half_rn(t[x][y + i]);
}

// ====================== LayerNorm (fp16 output for GEMM input) ============
template <bool FUSE_ADD>
__global__ __launch_bounds__(256) void ln_kernel(
    const float* __restrict__ x,
    const float* __restrict__ addend,
    float*       __restrict__ resid_out,
    const float* __restrict__ gamma,
    const float* __restrict__ beta,
    __half*      __restrict__ out)
{
    const int row = blockIdx.x;
    const int t   = threadIdx.x;
    const size_t base = (size_t)row * EMB;

    float4 v = *(const float4*)(x + base + t * 4);
    if (FUSE_ADD) {
        float4 a = *(const float4*)(addend + base + t * 4);
        v.x += a.x; v.y += a.y; v.z += a.z; v.w += a.w;
        *(float4*)(resid_out + base + t * 4) = v;
    }
    float s  = v.x + v.y + v.z + v.w;
    float ss = v.x*v.x + v.y*v.y + v.z*v.z + v.w*v.w;

    #pragma unroll
    for (int off = 16; off; off >>= 1) {
        s  += __shfl_down_sync(0xffffffffu, s,  off);
        ss += __shfl_down_sync(0xffffffffu, ss, off);
    }
    __shared__ float rs[8], rss[8];
    const int warp = t >> 5, lane = t & 31;
    if (lane == 0) { rs[warp] = s; rss[warp] = ss; }
    __syncthreads();
    if (t == 0) {
        float a = 0.f, b = 0.f;
        #pragma unroll
        for (int i = 0; i < 8; i++) { a += rs[i]; b += rss[i]; }
        rs[0] = a; rss[0] = b;
    }
    __syncthreads();
    const float mu  = rs[0] * (1.0f / EMB);
    const float var = rss[0] * (1.0f / EMB) - mu * mu;
    const float inv = rsqrtf(var + 1e-5f);

    float4 g  = *(const float4*)(gamma + t * 4);
    float4 b4 = *(const float4*)(beta  + t * 4);
    __half2 h0 = __floats2half2_rn((v.x - mu) * inv * g.x + b4.x,
                                   (v.y - mu) * inv * g.y + b4.y);
    __half2 h1 = __floats2half2_rn((v.z - mu) * inv * g.z + b4.z,
                                   (v.w - mu) * inv * g.w + b4.w);
    uint2 st;
    st.x = *(uint32_t*)&h0;
    st.y = *(uint32_t*)&h1;
    *(uint2*)(out + base + t * 4) = st;
}

// ====================== Flash attention (fp16 tensor cores) ================
// smem (halfs, row stride 72 = 144B): Q[64] | K0 K1 | Vstage0 Vstage1 | Vt
#define AQ_OFF      0
#define AK_OFF(s)   (9216 + (s) * 9216)
#define AVS_OFF(s)  (27648 + (s) * 9216)
#define AVT_OFF     46080
#define ATTN_SMEM   55296

__device__ __forceinline__ void load_q(uint32_t sb, const __half* __restrict__ kqv,
                                       int b, int h, int q0, int tid)
{
    const __half* qb = kqv + ((size_t)(b * SEQ + q0)) * 3072 + 1024 + h * 64;
    #pragma unroll
    for (int i = 0; i < 4; i++) {
        const int idx = tid + i * 128;
        const int row = idx >> 3, c = idx & 7;
        cpasync16(sb + AQ_OFF + (uint32_t)(row * 144 + c * 16), qb + (size_t)row * 3072 + c * 8);
    }
}

__device__ __forceinline__ void load_kv(uint32_t sb, const __half* __restrict__ kqv,
                                        int b, int h, int t, int buf, int tid)
{
    const __half* base = kqv + ((size_t)(b * SEQ + t * 64)) * 3072 + h * 64;
    const uint32_t kd = sb + AK_OFF(buf);
    const uint32_t vd = sb + AVS_OFF(buf);
    #pragma unroll
    for (int i = 0; i < 4; i++) {
        const int idx = tid + i * 128;
        const int row = idx >> 3, c = idx & 7;
        cpasync16(kd + (uint32_t)(row * 144 + c * 16), base + (size_t)row * 3072 + c * 8);
        cpasync16(vd + (uint32_t)(row * 144 + c * 16), base + (size_t)row * 3072 + 2048 + c * 8);
    }
}

// transpose Vstage[key][d] -> Vt[d][key] (fp16, stride 72 halfs both)
// conflict-free: rp=lane, c offset rotated by rp (banks 9*rp+const, 9 coprime 32)
__device__ __forceinline__ void transpose_v(uint32_t vs, uint32_t vt, int tid)
{
    const int rp = tid & 31;            // row pair (rows 2rp, 2rp+1)
    const int cb = (tid >> 5) << 3;     // c base: 0,8,16,24
    #pragma unroll
    for (int i = 0; i < 8; i++) {
        const int c = (cb + i + rp) & 31;   // d-pair index (d = 2c, 2c+1)
        const uint32_t a = lds_u32(vs + (uint32_t)(2 * rp) * 144 + c * 4);
        const uint32_t b = lds_u32(vs + (uint32_t)(2 * rp + 1) * 144 + c * 4);
        const uint32_t lo = __byte_perm(a, b, 0x5410);  // {a.h0, b.h0}
        const uint32_t hi = __byte_perm(a, b, 0x7632);  // {a.h1, b.h1}
        sts_u32(vt + (uint32_t)(2 * c) * 144 + rp * 4, lo);
        sts_u32(vt + (uint32_t)(2 * c + 1) * 144 + rp * 4, hi);
    }
}

__global__ __launch_bounds__(128) void attn_kernel(
    const __half* __restrict__ kqv, float* __restrict__ out)
{
    extern __shared__ __align__(16) char asmem[];
    const uint32_t sb = smem_u32(asmem);
    const int bx = (int)gridDim.x - 1 - (int)blockIdx.x;   // longest-first
    const int h = blockIdx.y, b = blockIdx.z;
    const int tid = threadIdx.x, w = tid >> 5, lane = tid & 31;
    const int tig = lane & 3, grp = lane >> 2;
    const float LOG2E = 1.4426950408889634f;
    const float qs2    = LOG2E / 32.0f;                    // scale/log2e fold
    const float slope2 = exp2f(-0.5f * (float)(h + 1)) * LOG2E;
    const int q0 = bx * 64;
    const int nt = bx + 1;

    load_q(sb, kqv, b, h, q0, tid);
    load_kv(sb, kqv, b, h, 0, 0, tid);
    CP_COMMIT();
    if (nt > 1) { load_kv(sb, kqv, b, h, 1, 1, tid); CP_COMMIT(); CP_WAIT(1); }
    else        { CP_WAIT(0); }
    __syncthreads();

    // Q fragments (raw fp16; scale applied post-mma)
    uint32_t qa[4][4];
    {
        const uint32_t qbase = sb + AQ_OFF + (uint32_t)(w * 16 + grp) * 144 + tig * 4;
        #pragma unroll
        for (int kk = 0; kk < 4; kk++) {
            qa[kk][0] = lds_u32(qbase + kk * 32);
            qa[kk][1] = lds_u32(qbase + 8 * 144 + kk * 32);
            qa[kk][2] = lds_u32(qbase + kk * 32 + 16);
            qa[kk][3] = lds_u32(qbase + 8 * 144 + kk * 32 + 16);
        }
    }

    float o[8][4];
    #pragma unroll
    for (int nf = 0; nf < 8; nf++) { o[nf][0] = o[nf][1] = o[nf][2] = o[nf][3] = 0.f; }
    float m0 = -INFINITY, m1 = -INFINITY, l0 = 0.f, l1 = 0.f;
    const int qrow = q0 + w * 16 + grp;

    for (int t = 0; t < nt; t++) {
        const uint32_t Ks = sb + AK_OFF(t & 1);
        const uint32_t Vt = sb + AVT_OFF;
        const bool diag = (t == nt - 1);

        // Vstage -> Vt (this tile's data already arrived; all warps past prev Vt reads)
        transpose_v(sb + AVS_OFF(t & 1), Vt, tid);
        __syncthreads();

        // S = Q K^T
        float s[8][4];
        #pragma unroll
        for (int nf = 0; nf < 8; nf++) { s[nf][0] = s[nf][1] = s[nf][2] = s[nf][3] = 0.f; }
        #pragma unroll
        for (int kk = 0; kk < 4; kk++) {
            #pragma unroll
            for (int nf = 0; nf < 8; nf++) {
                uint32_t kb[2];
                const uint32_t ka = Ks + (uint32_t)(nf * 8 + grp) * 144 + kk * 32 + tig * 4;
                kb[0] = lds_u32(ka);
                kb[1] = lds_u32(ka + 16);
                mma_f16(s[nf], qa[kk], kb);
            }
        }

        // scale + ALiBi + causal mask + tile max
        float mx0 = -INFINITY, mx1 = -INFINITY;
        #pragma unroll
        for (int nf = 0; nf < 8; nf++) {
            #pragma unroll
            for (int e = 0; e < 2; e++) {
                const int key = t * 64 + nf * 8 + 2 * tig + e;
                const float r0f = (float)(key - qrow);
                const float r1f = r0f - 8.0f;
                float v0 = fmaf(s[nf][e],     qs2, slope2 * r0f);
                float v1 = fmaf(s[nf][e + 2], qs2, slope2 * r1f);
                if (diag) {
                    if (r0f > 0.f) v0 = -1e30f;
                    if (r1f > 0.f) v1 = -1e30f;
                }
                s[nf][e] = v0; s[nf][e + 2] = v1;
                mx0 = fmaxf(mx0, v0); mx1 = fmaxf(mx1, v1);
            }
        }
        mx0 = fmaxf(mx0, __shfl_xor_sync(~0u, mx0, 1));
        mx0 = fmaxf(mx0, __shfl_xor_sync(~0u, mx0, 2));
        mx1 = fmaxf(mx1, __shfl_xor_sync(~0u, mx1, 1));
        mx1 = fmaxf(mx1, __shfl_xor_sync(~0u, mx1, 2));
        const float mn0 = fmaxf(m0, mx0), mn1 = fmaxf(m1, mx1);
        const float c0 = ex2(m0 - mn0), c1 = ex2(m1 - mn1);
        m0 = mn0; m1 = mn1;

        float rs0 = 0.f, rs1 = 0.f;
        #pragma unroll
        for (int nf = 0; nf < 8; nf++) {
            #pragma unroll
            for (int e = 0; e < 2; e++) {
                const float p0 = ex2(s[nf][e] - m0);
                const float p1 = ex2(s[nf][e + 2] - m1);
                s[nf][e] = p0; s[nf][e + 2] = p1;
                rs0 += p0; rs1 += p1;
            }
        }
        rs0 += __shfl_xor_sync(~0u, rs0, 1); rs0 += __shfl_xor_sync(~0u, rs0, 2);
        rs1 += __shfl_xor_sync(~0u, rs1, 1); rs1 += __shfl_xor_sync(~0u, rs1, 2);
        l0 = l0 * c0 + rs0; l1 = l1 * c1 + rs1;

        #pragma unroll
        for (int nf = 0; nf < 8; nf++) {
            o[nf][0] *= c0; o[nf][1] *= c0; o[nf][2] *= c1; o[nf][3] *= c1;
        }

        // O += P V : fp16 A-fragments come straight from C-layout (no shuffles)
        #pragma unroll
        for (int kk = 0; kk < 4; kk++) {
            uint32_t pa[4];
            pa[0] = pack_h2(s[2 * kk][0],     s[2 * kk][1]);
            pa[1] = pack_h2(s[2 * kk][2],     s[2 * kk][3]);
            pa[2] = pack_h2(s[2 * kk + 1][0], s[2 * kk + 1][1]);
            pa[3] = pack_h2(s[2 * kk + 1][2], s[2 * kk + 1][3]);
            #pragma unroll
            for (int nf = 0; nf < 8; nf++) {
                uint32_t vb[2];
                const uint32_t va = Vt + (uint32_t)(nf * 8 + grp) * 144 + kk * 32 + tig * 4;
                vb[0] = lds_u32(va);
                vb[1] = lds_u32(va + 16);
                mma_f16(o[nf], pa, vb);
            }
        }

        __syncthreads();
        if (t + 1 < nt) {
            if (t + 2 < nt) { load_kv(sb, kqv, b, h, t + 2, t & 1, tid); CP_COMMIT(); CP_WAIT(1); }
            else            { CP_WAIT(0); }
            __syncthreads();
        }
    }

    const float il0 = 1.0f / l0, il1 = 1.0f / l1;
    float* op = out + ((size_t)(b * SEQ + qrow)) * EMB + h * 64;
    #pragma unroll
    for (int nf = 0; nf < 8; nf++) {
        const int col = nf * 8 + 2 * tig;
        float2 u0 = make_float2(o[nf][0] * il0, o[nf][1] * il0);
        float2 u1 = make_float2(o[nf][2] * il1, o[nf][3] * il1);
        *(float2*)(op + col) = u0;
        *(float2*)(op + (size_t)8 * EMB + col) = u1;
    }
}

// ====================== host: tensor maps ==================================
typedef CUresult (*EncodeTiledFn)(
    CUtensorMap*, CUtensorMapDataType, cuuint32_t, void*,
    const cuuint64_t*, const cuuint64_t*, const cuuint32_t*, const cuuint32_t*,
    CUtensorMapInterleave, CUtensorMapSwizzle, CUtensorMapL2promotion,
    CUtensorMapFloatOOBfill);

static void make_map_f16(EncodeTiledFn enc, CUtensorMap* m, const __half* p,
                         int K, int rows, int boxRows) {
    cuuint64_t dims[2]    = {(cuuint64_t)K, (cuuint64_t)rows};
    cuuint64_t strides[1] = {(cuuint64_t)K * 2};
    cuuint32_t box[2]     = {(cuuint32_t)GBK, (cuuint32_t)boxRows};
    cuuint32_t es[2]      = {1, 1};
    enc(m, CU_TENSOR_MAP_DATA_TYPE_FLOAT16, 2, (void*)p, dims, strides, box, es,
        CU_TENSOR_MAP_INTERLEAVE_NONE, CU_TENSOR_MAP_SWIZZLE_128B,
        CU_TENSOR_MAP_L2_PROMOTION_L2_128B, CU_TENSOR_MAP_FLOAT_OOB_FILL_NONE);
}

// ====================== driver =============================================
extern "C" void kernel_launch(void* const* d_in, const int* in_sizes, int n_in,
                              void* d_out, int out_size)
{
    const float* x     = (const float*)d_in[0];
    const float* w_kqv = (const float*)d_in[1];
    const float* ln1_g = (const float*)d_in[2];
    const float* ln1_b = (const float*)d_in[3];
    const float* ln2_g = (const float*)d_in[4];
    const float* ln2_b = (const float*)d_in[5];
    const float* w1    = (const float*)d_in[6];
    const float* b1    = (const float*)d_in[7];
    const float* w2    = (const float*)d_in[8];
    const float* b2    = (const float*)d_in[9];
    float* out = (float*)d_out;

    __half *xn, *kqv, *hbuf, *mid, *wkqvT, *w1T, *w2T;
    float *attn;
    cudaGetSymbolAddress((void**)&xn,    g_xn);
    cudaGetSymbolAddress((void**)&kqv,   g_kqv);
    cudaGetSymbolAddress((void**)&attn,  g_attn);
    cudaGetSymbolAddress((void**)&hbuf,  g_h);
    cudaGetSymbolAddress((void**)&mid,   g_mid);
    cudaGetSymbolAddress((void**)&wkqvT, g_wkqvT);
    cudaGetSymbolAddress((void**)&w1T,   g_w1T);
    cudaGetSymbolAddress((void**)&w2T,   g_w2T);

    EncodeTiledFn enc = nullptr;
    {
        cudaDriverEntryPointQueryResult st;
        cudaGetDriverEntryPointByVersion("cuTensorMapEncodeTiled", (void**)&enc,
                                         12000, cudaEnableDefault, &st);
    }

    alignas(64) CUtensorMap mA1, mB1, mA2, mB2, mA3, mB3;
    make_map_f16(enc, &mA1, xn,    EMB, ROWS,    GBM);
    make_map_f16(enc, &mB1, wkqvT, EMB, 3 * EMB, GBN);
    make_map_f16(enc, &mA2, hbuf,  EMB, ROWS,    GBM);
    make_map_f16(enc, &mB2, w1T,   EMB, DFF,     GBN);
    make_map_f16(enc, &mA3, mid,   DFF, ROWS,    GBM);
    make_map_f16(enc, &mB3, w2T,   DFF, EMB,     GBN);

    cudaFuncSetAttribute(gemm_f16_kernel<true, false, false, false>,
                         cudaFuncAttributeMaxDynamicSharedMemorySize, GEMM_SMEM_TOTAL);
    cudaFuncSetAttribute(gemm_f16_kernel<true, true, true, false>,
                         cudaFuncAttributeMaxDynamicSharedMemorySize, GEMM_SMEM_TOTAL);
    cudaFuncSetAttribute(gemm_f16_kernel<false, true, false, true>,
                         cudaFuncAttributeMaxDynamicSharedMemorySize, GEMM_SMEM_TOTAL);
    cudaFuncSetAttribute(attn_kernel,
                         cudaFuncAttributeMaxDynamicSharedMemorySize, ATTN_SMEM);

    // 0) weight transposes -> fp16 [N,K]
    transpose_kernel<<<dim3(3 * EMB / 32, EMB / 32), dim3(32, 8)>>>(w_kqv, wkqvT, EMB, 3 * EMB);
    transpose_kernel<<<dim3(DFF / 32, EMB / 32), dim3(32, 8)>>>(w1, w1T, EMB, DFF);
    transpose_kernel<<<dim3(EMB / 32, DFF / 32), dim3(32, 8)>>>(w2, w2T, DFF, EMB);

    // 1) LN1 -> fp16
    ln_kernel<false><<<ROWS, 256>>>(x, nullptr, nullptr, ln1_g, ln1_b, xn);

    // 2) kqv = xn @ w_kqv  (fp16 out)
    gemm_f16_kernel<true, false, false, false>
        <<<dim3(3 * EMB / GBN, ROWS / GBM), 288, GEMM_SMEM_TOTAL>>>(
            mA1, mB1, nullptr, nullptr, kqv, 3 * EMB, EMB);

    // 3) attention (fp16 tensor cores)
    attn_kernel<<<dim3(SEQ / 64, NH, BATCH), 128, ATTN_SMEM>>>(kqv, attn);

    // 4) x1 = x + attn (-> out), h = LN2(x1) -> fp16
    ln_kernel<true><<<ROWS, 256>>>(x, attn, out, ln2_g, ln2_b, hbuf);

    // 5) mid = relu(h @ w1 + b1) -> fp16
    gemm_f16_kernel<true, true, true, false>
        <<<dim3(DFF / GBN, ROWS / GBM), 288, GEMM_SMEM_TOTAL>>>(
            mA2, mB2, b1, nullptr, mid, DFF, EMB);

    // 6) out = x1 + mid @ w2 + b2  (fp32 out + residual)
    gemm_f16_kernel<false, true, false, true>
        <<<dim3(EMB / GBN, ROWS / GBM), 288, GEMM_SMEM_TOTAL>>>(
            mA3, mB3, b2, out, out, EMB, DFF);

    (void)in_sizes; (void)n_in; (void)out_size;
}